// round 9
// baseline (speedup 1.0000x reference)
#include <cuda_runtime.h>
#include <cuda_bf16.h>
#include <math.h>
#include <stdint.h>

#define T_STEPS 400
#define BATCH   256
#define NH      512
#define NCTA    128
#define NTHR    512

// ---- smem layout (bytes) ----
#define B_HALF  18432                 // one 128x72(bf16) tile image
#define B_TILE  36864                 // hi+lo
#define SM_B0   0                     // 3 rotating B buffers
#define SM_A    110592                // 2 A buffers x (hi 8704 + lo 8704)
#define A_BUF   17408
#define A_HALF  8704
#define SM_RED  145408                // 4 x (32 x 68 fp32)
#define SM_TOTAL 180224

// ---- persistent device buffers (no cudaMalloc allowed) ----
__device__ __align__(16) __nv_bfloat16 g_Bhi[640*9216];   // 40 sched-slots x 16 jb x (128x72)
__device__ __align__(16) __nv_bfloat16 g_Blo[640*9216];
__device__ __align__(16) float g_h [BATCH*NH];
__device__ __align__(16) float g_s0[BATCH*NH];
__device__ __align__(16) float g_s1[BATCH*NH];
__device__ __align__(16) float g_s2[BATCH*NH];
__device__ __align__(16) float g_s3[BATCH*NH];
__device__ __align__(16) float g_s5[BATCH*NH];
__device__ unsigned long long g_bar = 0;                  // monotonic -> graph-replay safe

// ---- asm helpers ----
__device__ __forceinline__ uint32_t smem_u32(const void* p) {
    uint32_t a;
    asm("{ .reg .u64 t; cvta.to.shared.u64 t, %1; cvt.u32.u64 %0, t; }" : "=r"(a) : "l"(p));
    return a;
}
#define CPA16(d, s) asm volatile("cp.async.cg.shared.global [%0], [%1], 16;" :: "r"(d), "l"(s))
#define CPCOMMIT()  asm volatile("cp.async.commit_group;" ::: "memory")
#define CPWAIT1()   asm volatile("cp.async.wait_group 1;" ::: "memory")
#define LDM4(r, a) \
    asm volatile("ldmatrix.sync.aligned.m8n8.x4.shared.b16 {%0,%1,%2,%3}, [%4];" \
        : "=r"((r)[0]), "=r"((r)[1]), "=r"((r)[2]), "=r"((r)[3]) : "r"(a))
#define LDM4T(r, a) \
    asm volatile("ldmatrix.sync.aligned.m8n8.x4.trans.shared.b16 {%0,%1,%2,%3}, [%4];" \
        : "=r"((r)[0]), "=r"((r)[1]), "=r"((r)[2]), "=r"((r)[3]) : "r"(a))
#define MMAB(d, a, b0, b1) \
    asm volatile("mma.sync.aligned.m16n8k16.row.col.f32.bf16.bf16.f32 " \
        "{%0,%1,%2,%3},{%4,%5,%6,%7},{%8,%9},{%0,%1,%2,%3};" \
        : "+f"((d)[0]), "+f"((d)[1]), "+f"((d)[2]), "+f"((d)[3]) \
        : "r"((a)[0]), "r"((a)[1]), "r"((a)[2]), "r"((a)[3]), "r"(b0), "r"(b1))

__device__ __forceinline__ void grid_barrier() {
    __syncthreads();
    if (threadIdx.x == 0) {
        __threadfence();
        unsigned long long arr    = atomicAdd(&g_bar, 1ULL);
        unsigned long long target = (arr / NCTA + 1ULL) * NCTA;
        while (*(volatile unsigned long long*)&g_bar < target) { __nanosleep(64); }
        __threadfence();
    }
    __syncthreads();
}

__device__ __forceinline__ float sigf(float x) { return 1.0f / (1.0f + expf(-x)); }

// Prefetch the B tile for flat chunk q into rotating buffer q%3.
__device__ __forceinline__ void issue_tile(int q, int tid, int jb, uint32_t smu) {
    int sp = q % 40, slot = q % 3;
    const char* gh = (const char*)g_Bhi + ((size_t)sp * 16 + jb) * 18432;
    const char* gl = (const char*)g_Blo + ((size_t)sp * 16 + jb) * 18432;
    uint32_t dst = smu + SM_B0 + slot * B_TILE;
    #pragma unroll
    for (int i = 0; i < 5; ++i) {
        int idx = tid + i * NTHR;               // 0..2559, 2304 valid
        if (idx < 1152)       CPA16(dst + idx * 16, gh + (size_t)idx * 16);
        else if (idx < 2304)  CPA16(dst + B_HALF + (idx - 1152) * 16, gl + (size_t)(idx - 1152) * 16);
    }
    CPCOMMIT();
}

// A chunk staging, split: global loads into regs / convert + store to smem buffer.
__device__ __forceinline__ void stage_load(float4 pre[2], const float* __restrict__ asrc,
                                           int row_base, int koff, int tid) {
    #pragma unroll
    for (int it = 0; it < 2; ++it) {
        int idx = tid + it * NTHR;              // 0..1023
        int r = idx >> 5, k4 = idx & 31;
        pre[it] = *(const float4*)(asrc + (size_t)(row_base + r) * NH + koff + k4 * 4);
    }
}
__device__ __forceinline__ void stage_store(const float4 pre[2], char* abuf, int tid) {
    #pragma unroll
    for (int it = 0; it < 2; ++it) {
        int idx = tid + it * NTHR;
        int r = idx >> 5, k4 = idx & 31;
        float4 v = pre[it];
        __nv_bfloat16 h0 = __float2bfloat16(v.x), h1 = __float2bfloat16(v.y),
                      h2 = __float2bfloat16(v.z), h3 = __float2bfloat16(v.w);
        __nv_bfloat16 l0 = __float2bfloat16(v.x - __bfloat162float(h0));
        __nv_bfloat16 l1 = __float2bfloat16(v.y - __bfloat162float(h1));
        __nv_bfloat16 l2 = __float2bfloat16(v.z - __bfloat162float(h2));
        __nv_bfloat16 l3 = __float2bfloat16(v.w - __bfloat162float(h3));
        uint32_t ph0 = ((uint32_t)__bfloat16_as_ushort(h1) << 16) | __bfloat16_as_ushort(h0);
        uint32_t ph1 = ((uint32_t)__bfloat16_as_ushort(h3) << 16) | __bfloat16_as_ushort(h2);
        uint32_t pl0 = ((uint32_t)__bfloat16_as_ushort(l1) << 16) | __bfloat16_as_ushort(l0);
        uint32_t pl1 = ((uint32_t)__bfloat16_as_ushort(l3) << 16) | __bfloat16_as_ushort(l2);
        char* ab = abuf + r * 272 + k4 * 8;
        *(uint2*)ab            = make_uint2(ph0, ph1);
        *(uint2*)(ab + A_HALF) = make_uint2(pl0, pl1);
    }
}

// One K=128 chunk of HMMA. Warp (kh,nw): kh quarter of ksteps (2 of 8), n cols {nw*8 (c), 32+nw*8 (h)}.
__device__ __forceinline__ void mma_chunk(uint32_t smu, int slot, int abuf_off,
                                          int lane, int kh, int nw, float acc[2][2][4]) {
    uint32_t Bb = smu + SM_B0 + slot * B_TILE;
    uint32_t Ab = smu + SM_A + abuf_off;
    int l15 = lane & 15, l16 = lane >> 4;
    #pragma unroll
    for (int ksl = 0; ksl < 2; ++ksl) {
        int ks = kh * 2 + ksl;
        uint32_t ah[2][4], al[2][4], bh[4], bl[4];
        uint32_t kb = (uint32_t)(ks * 16 + l16 * 8) * 2;
        #pragma unroll
        for (int mf = 0; mf < 2; ++mf) {
            uint32_t aa = Ab + (uint32_t)(mf * 16 + l15) * 272 + kb;
            LDM4(ah[mf], aa);
            LDM4(al[mf], aa + A_HALF);
        }
        uint32_t ba = Bb + (uint32_t)(ks * 16 + l15) * 144 + (uint32_t)(nw * 32 + l16 * 16);
        LDM4T(bh, ba);
        LDM4T(bl, ba + B_HALF);
        #pragma unroll
        for (int mf = 0; mf < 2; ++mf) {
            MMAB(acc[mf][0], ah[mf], bh[0], bh[1]);
            MMAB(acc[mf][0], ah[mf], bl[0], bl[1]);
            MMAB(acc[mf][0], al[mf], bh[0], bh[1]);
            MMAB(acc[mf][1], ah[mf], bh[2], bh[3]);
            MMAB(acc[mf][1], ah[mf], bl[2], bl[3]);
            MMAB(acc[mf][1], al[mf], bh[2], bh[3]);
        }
    }
}

// One GEMM level: nch K=128 chunks, pipelined A staging, ONE sync per chunk.
// Ordering invariant: issue_tile(n+2) is placed AFTER the chunk sync so slot
// (n+2)%3 == (n-1)%3 is provably no longer being read by any warp's mma(n-1).
// CPWAIT1 (<=1 pending group) then guarantees tile n resident (n+1 in flight).
__device__ __forceinline__ void run_level(int nch, const float* aA, const float* aB,
                                          char* sm, uint32_t smu, int tid, int lane,
                                          int kh, int nw, int row_base, int jb,
                                          int& n, float acc[2][2][4]) {
    #pragma unroll
    for (int mf = 0; mf < 2; ++mf)
        #pragma unroll
        for (int nf = 0; nf < 2; ++nf)
            #pragma unroll
            for (int e = 0; e < 4; ++e) acc[mf][nf][e] = 0.f;
    float4 pre[2];
    stage_load(pre, aA, row_base, 0, tid);
    stage_store(pre, sm + SM_A, tid);                       // buf 0 <- chunk 0
    for (int c = 0; c < nch; ++c) {
        bool more = (c + 1) < nch;
        if (more)
            stage_load(pre, ((c + 1) < 4) ? aA : aB, row_base, ((c + 1) & 3) * 128, tid);
        CPWAIT1();
        __syncthreads();                                    // A[c&1] staged; B slot n%3 resident; mma(n-1) reads done
        issue_tile(n + 2, tid, jb, smu);                    // overwrites slot (n-1)%3 — now free
        if (more) stage_store(pre, sm + SM_A + ((c + 1) & 1) * A_BUF, tid);
        mma_chunk(smu, n % 3, (c & 1) * A_BUF, lane, kh, nw, acc);
        ++n;
    }
}

// Reduce 4 k-partials via smem, apply highway gate, store state + mean.
// act: 0 tanh, 1 relu, 2 sigmoid, 3 identity.
__device__ __forceinline__ void red_epilogue(char* sm, const float acc[2][2][4],
                                             int lane, int kh, int nw, int tid,
                                             const float* __restrict__ sp_src, float* sdst,
                                             int act, bool do_mean, float mean[2],
                                             int grow, int gcol) {
    __syncthreads();                                        // all mma done before red overwrite
    float* red = (float*)(sm + SM_RED) + kh * 2176;         // 32 x 68
    int g = lane >> 2, t4 = lane & 3;
    #pragma unroll
    for (int mf = 0; mf < 2; ++mf)
        #pragma unroll
        for (int nf = 0; nf < 2; ++nf) {
            int row = mf * 16 + g, col = nf * 32 + nw * 8 + t4 * 2;
            *(float2*)(red + row * 68 + col)       = make_float2(acc[mf][nf][0], acc[mf][nf][1]);
            *(float2*)(red + (row + 8) * 68 + col) = make_float2(acc[mf][nf][2], acc[mf][nf][3]);
        }
    __syncthreads();
    int er = tid >> 4, ej = (tid & 15) * 2;
    float c0 = 0.f, c1 = 0.f, h0 = 0.f, h1 = 0.f;
    #pragma unroll
    for (int p = 0; p < 4; ++p) {
        const float* r = (const float*)(sm + SM_RED) + p * 2176 + er * 68;
        float2 pc = *(const float2*)(r + ej);
        float2 ph = *(const float2*)(r + 32 + ej);
        c0 += pc.x; c1 += pc.y; h0 += ph.x; h1 += ph.y;
    }
    float2 sp = *(const float2*)(sp_src + (size_t)grow * NH + gcol);
    float hv0 = (act == 0) ? tanhf(h0) : (act == 1) ? fmaxf(h0, 0.f) : (act == 2) ? sigf(h0) : h0;
    float hv1 = (act == 0) ? tanhf(h1) : (act == 1) ? fmaxf(h1, 0.f) : (act == 2) ? sigf(h1) : h1;
    float s0 = sp.x + sigf(c0) * (hv0 - sp.x);
    float s1 = sp.y + sigf(c1) * (hv1 - sp.y);
    if (do_mean) { mean[0] += s0; mean[1] += s1; }
    if (sdst) *(float2*)(sdst + (size_t)grow * NH + gcol) = make_float2(s0, s1);
}

// ---- prepass: pack weights to bf16 hi/lo tiles in the exact smem image ----
__global__ void prepack_kernel(const float* __restrict__ W0, const float* __restrict__ Ws) {
    const int lvl_order[8] = {0, 1, 2, 3, 4, 6, 5, 7};
    const int total = 640 * 128 * 8;                       // (tile, krow, 8-col group)
    for (int idx = blockIdx.x * blockDim.x + threadIdx.x; idx < total; idx += gridDim.x * blockDim.x) {
        int g8 = idx & 7;
        int kr = (idx >> 3) & 127;
        int tt = idx >> 10;                                 // 0..639
        int sp = tt >> 4, jb = tt & 15;
        const float* src; int kbase;
        if (sp < 8) { src = W0; kbase = sp * 128; }
        else { int sp2 = sp - 8; src = Ws + (size_t)lvl_order[sp2 >> 2] * 512 * 1024; kbase = (sp2 & 3) * 128; }
        __align__(16) __nv_bfloat16 hb[8], lb[8];
        #pragma unroll
        for (int e = 0; e < 8; ++e) {
            int cidx = g8 * 8 + e;
            int nw2 = cidx >> 4, w16 = cidx & 15;          // permuted: [c0..7 | h0..7] per n-warp
            int gc = (w16 < 8) ? (jb * 32 + nw2 * 8 + w16)
                               : (512 + jb * 32 + nw2 * 8 + (w16 - 8));
            float wv = src[(size_t)(kbase + kr) * 1024 + gc];
            __nv_bfloat16 h = __float2bfloat16(wv);
            hb[e] = h;
            lb[e] = __float2bfloat16(wv - __bfloat162float(h));
        }
        size_t boff = (size_t)tt * 18432 + kr * 144 + g8 * 16;
        *(uint4*)((char*)g_Bhi + boff) = *(const uint4*)hb;
        *(uint4*)((char*)g_Blo + boff) = *(const uint4*)lb;
    }
}

__global__ void __launch_bounds__(NTHR, 1)
rnn_kernel(const float* __restrict__ inputs, const float* __restrict__ hidden0,
           float* __restrict__ out) {
    extern __shared__ char sm[];
    uint32_t smu = smem_u32(sm);
    int tid = threadIdx.x, lane = tid & 31, warp = tid >> 5;
    int kh = warp >> 2, nw = warp & 3;                      // 4 k-quarters x 4 n-warps
    int rb = blockIdx.x >> 4, jb = blockIdx.x & 15;
    int row_base = rb * 32, colc = jb * 32;
    int er = tid >> 4, ej = (tid & 15) * 2;
    int grow = row_base + er, gcol = colc + ej;

    int n = 0;
    issue_tile(0, tid, jb, smu);
    issue_tile(1, tid, jb, smu);

    float acc[2][2][4];
    for (int t = 0; t < T_STEPS; ++t) {
        const float* x    = inputs + (size_t)t * BATCH * NH;
        const float* hsrc = t ? g_h : hidden0;
        float mean[2] = {0.f, 0.f};

        // L0: s0 = highway(concat(x,h) @ W0), K=1024
        run_level(8, x, hsrc, sm, smu, tid, lane, kh, nw, row_base, jb, n, acc);
        red_epilogue(sm, acc, lane, kh, nw, tid, hsrc, g_s0, 0, false, mean, grow, gcol);
        grid_barrier();
        // n1 = gate(s0 @ Ws0, tanh)
        run_level(4, g_s0, g_s0, sm, smu, tid, lane, kh, nw, row_base, jb, n, acc);
        red_epilogue(sm, acc, lane, kh, nw, tid, g_s0, g_s1, 0, true, mean, grow, gcol);
        grid_barrier();
        // n2,n3,n4 (pred s1): relu, relu, identity
        run_level(4, g_s1, g_s1, sm, smu, tid, lane, kh, nw, row_base, jb, n, acc);
        red_epilogue(sm, acc, lane, kh, nw, tid, g_s1, g_s2, 1, true, mean, grow, gcol);
        run_level(4, g_s1, g_s1, sm, smu, tid, lane, kh, nw, row_base, jb, n, acc);
        red_epilogue(sm, acc, lane, kh, nw, tid, g_s1, g_s3, 1, true, mean, grow, gcol);
        run_level(4, g_s1, g_s1, sm, smu, tid, lane, kh, nw, row_base, jb, n, acc);
        red_epilogue(sm, acc, lane, kh, nw, tid, g_s1, (float*)0, 3, true, mean, grow, gcol);
        grid_barrier();
        // n5 = gate(s2 @ Ws4, tanh); n7 = gate(s3 @ Ws6, tanh)
        run_level(4, g_s2, g_s2, sm, smu, tid, lane, kh, nw, row_base, jb, n, acc);
        red_epilogue(sm, acc, lane, kh, nw, tid, g_s2, g_s5, 0, true, mean, grow, gcol);
        run_level(4, g_s3, g_s3, sm, smu, tid, lane, kh, nw, row_base, jb, n, acc);
        red_epilogue(sm, acc, lane, kh, nw, tid, g_s3, (float*)0, 0, true, mean, grow, gcol);
        grid_barrier();
        // n6 = gate(s5 @ Ws5, sigmoid); n8 = gate(s5 @ Ws7, relu)
        run_level(4, g_s5, g_s5, sm, smu, tid, lane, kh, nw, row_base, jb, n, acc);
        red_epilogue(sm, acc, lane, kh, nw, tid, g_s5, (float*)0, 2, true, mean, grow, gcol);
        run_level(4, g_s5, g_s5, sm, smu, tid, lane, kh, nw, row_base, jb, n, acc);
        red_epilogue(sm, acc, lane, kh, nw, tid, g_s5, (float*)0, 1, true, mean, grow, gcol);

        // finalize: h = mean(states 1..8)
        float2 hv = make_float2(mean[0] * 0.125f, mean[1] * 0.125f);
        *(float2*)(g_h + (size_t)grow * NH + gcol) = hv;
        *(float2*)(out + ((size_t)t * BATCH + grow) * NH + gcol) = hv;
        if (t == T_STEPS - 1)
            *(float2*)(out + (size_t)T_STEPS * BATCH * NH + (size_t)grow * NH + gcol) = hv;
        grid_barrier();
    }
}

extern "C" void kernel_launch(void* const* d_in, const int* in_sizes, int n_in,
                              void* d_out, int out_size) {
    const float* inputs = (const float*)d_in[0];
    const float* hidden = (const float*)d_in[1];
    const float* W0     = (const float*)d_in[2];
    const float* Ws     = (const float*)d_in[3];
    float* out = (float*)d_out;

    prepack_kernel<<<512, 256>>>(W0, Ws);
    cudaFuncSetAttribute(rnn_kernel, cudaFuncAttributeMaxDynamicSharedMemorySize, SM_TOTAL);
    rnn_kernel<<<NCTA, NTHR, SM_TOTAL>>>(inputs, hidden, out);
}

// round 10
// speedup vs baseline: 1.3218x; 1.3218x over previous
#include <cuda_runtime.h>
#include <cuda_bf16.h>
#include <math.h>
#include <stdint.h>

#define T_STEPS 400
#define BATCH   256
#define NH      512
#define NCTA    128
#define NTHR    512
#define TOT_CHUNKS (T_STEPS*40)

// ---- tile images ----
#define A_IMG   17408                 // 32 rows x 272B (hi 8704) + lo 8704
#define A_HALF  8704
#define B_IMG   36864                 // 128 rows x 144B (hi 18432) + lo 18432
#define B_HALF  18432

// ---- smem layout (bytes) ----
#define SM_B0   0                     // 3 rotating B slots
#define SM_A    110592                // 2 rotating A slots
#define SM_RED  145408                // 4 x 8704 partials
#define SM_BAR  180224                // 3 B mbarriers + 2 A mbarriers (8B each)
#define SM_TOTAL 180352

// ---- persistent device buffers (no cudaMalloc allowed) ----
__device__ __align__(16) char g_Bpk[640ull*B_IMG];          // 40 sched-slots x 16 jb
__device__ __align__(16) char g_st[6ull*8*4*A_IMG];         // states s0,s1,s2,s3,s5,h : [st][rb][chunk]
__device__ unsigned long long g_barr[8*32];                 // rb-local barrier counters (monotonic)

// ---- asm helpers ----
__device__ __forceinline__ uint32_t smem_u32(const void* p) {
    uint32_t a;
    asm("{ .reg .u64 t; cvta.to.shared.u64 t, %1; cvt.u32.u64 %0, t; }" : "=r"(a) : "l"(p));
    return a;
}
#define LDM4(r, a) \
    asm volatile("ldmatrix.sync.aligned.m8n8.x4.shared.b16 {%0,%1,%2,%3}, [%4];" \
        : "=r"((r)[0]), "=r"((r)[1]), "=r"((r)[2]), "=r"((r)[3]) : "r"(a))
#define LDM4T(r, a) \
    asm volatile("ldmatrix.sync.aligned.m8n8.x4.trans.shared.b16 {%0,%1,%2,%3}, [%4];" \
        : "=r"((r)[0]), "=r"((r)[1]), "=r"((r)[2]), "=r"((r)[3]) : "r"(a))
#define MMAB(d, a, b0, b1) \
    asm volatile("mma.sync.aligned.m16n8k16.row.col.f32.bf16.bf16.f32 " \
        "{%0,%1,%2,%3},{%4,%5,%6,%7},{%8,%9},{%0,%1,%2,%3};" \
        : "+f"((d)[0]), "+f"((d)[1]), "+f"((d)[2]), "+f"((d)[3]) \
        : "r"((a)[0]), "r"((a)[1]), "r"((a)[2]), "r"((a)[3]), "r"(b0), "r"(b1))

__device__ __forceinline__ void mbar_init(uint32_t bar, uint32_t cnt) {
    asm volatile("mbarrier.init.shared.b64 [%0], %1;" :: "r"(bar), "r"(cnt) : "memory");
}
__device__ __forceinline__ void mbar_wait(uint32_t bar, uint32_t parity) {
    asm volatile(
        "{\n\t.reg .pred P;\n\tWL_%=:\n\t"
        "mbarrier.try_wait.parity.acquire.cta.shared::cta.b64 P, [%0], %1;\n\t"
        "@P bra.uni WD_%=;\n\tbra.uni WL_%=;\n\tWD_%=:\n\t}"
        :: "r"(bar), "r"(parity) : "memory");
}
__device__ __forceinline__ void bulk_g2s(uint32_t dst, const void* src, uint32_t bytes, uint32_t bar) {
    asm volatile("mbarrier.arrive.expect_tx.shared.b64 _, [%0], %1;" :: "r"(bar), "r"(bytes) : "memory");
    asm volatile("cp.async.bulk.shared::cta.global.mbarrier::complete_tx::bytes [%0], [%1], %2, [%3];"
                 :: "r"(dst), "l"(src), "r"(bytes), "r"(bar) : "memory");
}

__device__ __forceinline__ void grid_barrier(int rb) {
    __syncthreads();
    if (threadIdx.x == 0) {
        __threadfence();
        unsigned long long* ctr = &g_barr[rb * 32];
        unsigned long long arr = atomicAdd(ctr, 1ULL);
        unsigned long long target = (arr / 16 + 1ULL) * 16;
        while (*(volatile unsigned long long*)ctr < target) { __nanosleep(32); }
        __threadfence();
    }
    __syncthreads();
}

__device__ __forceinline__ float sigf(float x) { return 1.0f / (1.0f + expf(-x)); }
__device__ __forceinline__ uint32_t pack_bf16x2(float a, float b) {
    __nv_bfloat16 ba = __float2bfloat16(a), bb = __float2bfloat16(b);
    return ((uint32_t)__bfloat16_as_ushort(bb) << 16) | __bfloat16_as_ushort(ba);
}
__device__ __forceinline__ float bf16lo(uint32_t w) {
    return __bfloat162float(__ushort_as_bfloat16((unsigned short)(w & 0xffff)));
}
__device__ __forceinline__ float bf16hi(uint32_t w) {
    return __bfloat162float(__ushort_as_bfloat16((unsigned short)(w >> 16)));
}

// B prefetch: one bulk per chunk, slot q%3, parity (q/3)&1 at wait.
__device__ __forceinline__ void issue_B(int q, int jb, uint32_t smu, int tid) {
    if (q >= TOT_CHUNKS) return;
    if (tid == 0) {
        uint32_t bar = smu + SM_BAR + (q % 3) * 8;
        uint32_t dst = smu + SM_B0 + (q % 3) * B_IMG;
        const char* src = g_Bpk + ((size_t)((q % 40) * 16 + jb)) * B_IMG;
        bulk_g2s(dst, src, B_IMG, bar);
    }
}
// A prefetch (packed state): slot 0/1; parity tracked via ua/ap (uniform across threads).
__device__ __forceinline__ void issue_A(int slot, const char* src, uint32_t smu, int tid,
                                        int& ua0, int& ua1, int& ap0, int& ap1) {
    if (slot == 0) { ap0 = ua0 & 1; ua0++; } else { ap1 = ua1 & 1; ua1++; }
    if (tid == 0) {
        uint32_t bar = smu + SM_BAR + 24 + slot * 8;
        uint32_t dst = smu + SM_A + slot * A_IMG;
        bulk_g2s(dst, src, A_IMG, bar);
    }
}

// x staging (L0 chunks 0-3 only): fp32 -> bf16 hi/lo tile image via LDG+STS.
__device__ __forceinline__ void stage_load(float4 pre[2], const float* __restrict__ asrc,
                                           int row_base, int koff, int tid) {
    #pragma unroll
    for (int it = 0; it < 2; ++it) {
        int idx = tid + it * NTHR;              // 0..1023
        int r = idx >> 5, k4 = idx & 31;
        pre[it] = *(const float4*)(asrc + (size_t)(row_base + r) * NH + koff + k4 * 4);
    }
}
__device__ __forceinline__ void stage_store(const float4 pre[2], char* abuf, int tid) {
    #pragma unroll
    for (int it = 0; it < 2; ++it) {
        int idx = tid + it * NTHR;
        int r = idx >> 5, k4 = idx & 31;
        float4 v = pre[it];
        __nv_bfloat16 h0 = __float2bfloat16(v.x), h1 = __float2bfloat16(v.y),
                      h2 = __float2bfloat16(v.z), h3 = __float2bfloat16(v.w);
        uint32_t ph0 = ((uint32_t)__bfloat16_as_ushort(h1) << 16) | __bfloat16_as_ushort(h0);
        uint32_t ph1 = ((uint32_t)__bfloat16_as_ushort(h3) << 16) | __bfloat16_as_ushort(h2);
        uint32_t pl0 = pack_bf16x2(v.x - __bfloat162float(h0), v.y - __bfloat162float(h1));
        uint32_t pl1 = pack_bf16x2(v.z - __bfloat162float(h2), v.w - __bfloat162float(h3));
        char* ab = abuf + r * 272 + k4 * 8;
        *(uint2*)ab            = make_uint2(ph0, ph1);
        *(uint2*)(ab + A_HALF) = make_uint2(pl0, pl1);
    }
}

// One K=128 chunk of HMMA. Warp (kh,nw): ks = kh*2+{0,1}; n cols {nw*8 (c), 32+nw*8 (h)}.
__device__ __forceinline__ void mma_chunk(uint32_t smu, int slot, int abuf_off,
                                          int lane, int kh, int nw, float acc[2][2][4]) {
    uint32_t Bb = smu + SM_B0 + slot * B_IMG;
    uint32_t Ab = smu + SM_A + abuf_off;
    int l15 = lane & 15, l16 = lane >> 4;
    #pragma unroll
    for (int ksl = 0; ksl < 2; ++ksl) {
        int ks = kh * 2 + ksl;
        uint32_t ah[2][4], al[2][4], bh[4], bl[4];
        uint32_t kb = (uint32_t)(ks * 16 + l16 * 8) * 2;
        #pragma unroll
        for (int mf = 0; mf < 2; ++mf) {
            uint32_t aa = Ab + (uint32_t)(mf * 16 + l15) * 272 + kb;
            LDM4(ah[mf], aa);
            LDM4(al[mf], aa + A_HALF);
        }
        uint32_t ba = Bb + (uint32_t)(ks * 16 + l15) * 144 + (uint32_t)(nw * 32 + l16 * 16);
        LDM4T(bh, ba);
        LDM4T(bl, ba + B_HALF);
        #pragma unroll
        for (int mf = 0; mf < 2; ++mf) {
            MMAB(acc[mf][0], ah[mf], bh[0], bh[1]);
            MMAB(acc[mf][0], ah[mf], bl[0], bl[1]);
            MMAB(acc[mf][0], al[mf], bh[0], bh[1]);
            MMAB(acc[mf][1], ah[mf], bh[2], bh[3]);
            MMAB(acc[mf][1], ah[mf], bl[2], bl[3]);
            MMAB(acc[mf][1], al[mf], bh[2], bh[3]);
        }
    }
}

// One GEMM level. bulk_start: first chunk whose A comes from packed state (0 = all, 4 = L0).
// Invariants: chunk c uses A slot c&1, B slot n%3; issue into a slot only after the
// sync following the mma that last read it; B(n+2) issued post-sync; A(c+1) issued at
// iter c (prologue covers A(0)[,A(1)]).
__device__ void run_level(int nch, int bulk_start, const float* xsrc, const char* abase,
                          char* sm, uint32_t smu, int tid, int lane, int kh, int nw,
                          int row_base, int jb, int& n,
                          int& ua0, int& ua1, int& ap0, int& ap1, float acc[2][2][4]) {
    #pragma unroll
    for (int mf = 0; mf < 2; ++mf)
        #pragma unroll
        for (int nf = 0; nf < 2; ++nf)
            #pragma unroll
            for (int e = 0; e < 4; ++e) acc[mf][nf][e] = 0.f;
    if (bulk_start == 0) {
        issue_A(0, abase,          smu, tid, ua0, ua1, ap0, ap1);
        issue_A(1, abase + A_IMG,  smu, tid, ua0, ua1, ap0, ap1);
    } else {
        float4 p0[2];
        stage_load(p0, xsrc, row_base, 0, tid);
        stage_store(p0, sm + SM_A, tid);
    }
    int thresh = bulk_start ? bulk_start : 2;
    for (int c = 0; c < nch; ++c) {
        int cb = c + 1;
        bool nx_x = (cb < nch) && (cb < bulk_start);
        float4 pre[2];
        if (nx_x) stage_load(pre, xsrc, row_base, cb * 128, tid);
        mbar_wait(smu + SM_BAR + (n % 3) * 8, (uint32_t)((n / 3) & 1));
        if (c >= bulk_start)
            mbar_wait(smu + SM_BAR + 24 + (c & 1) * 8, (uint32_t)((c & 1) ? ap1 : ap0));
        __syncthreads();                               // mma(c-1) done; slots rotatable
        issue_B(n + 2, jb, smu, tid);
        if (nx_x) stage_store(pre, sm + SM_A + (cb & 1) * A_IMG, tid);
        if (cb < nch && cb >= thresh)
            issue_A(cb & 1, abase + (size_t)(cb - bulk_start) * A_IMG, smu, tid, ua0, ua1, ap0, ap1);
        mma_chunk(smu, n % 3, (c & 1) * A_IMG, lane, kh, nw, acc);
        ++n;
    }
}

// Reduce 4 k-partials, gate vs sp (reconstructed bf16 hi+lo), store packed state.
__device__ void red_epilogue(char* sm, const float acc[2][2][4], int lane, int kh, int nw,
                             int tid, const char* sp_pk, char* dst_pk, int act, bool do_mean,
                             float mean[2], int er, int ej) {
    const char* spp = sp_pk + (ej >> 7) * A_IMG + er * 272 + (ej & 127) * 2;
    uint32_t hiw = *(const uint32_t*)spp;              // issued before syncs -> latency hidden
    uint32_t low = *(const uint32_t*)(spp + A_HALF);
    __syncthreads();
    float* red = (float*)(sm + SM_RED) + kh * 2176;    // 32 x 68
    int g = lane >> 2, t4 = lane & 3;
    #pragma unroll
    for (int mf = 0; mf < 2; ++mf)
        #pragma unroll
        for (int nf = 0; nf < 2; ++nf) {
            int row = mf * 16 + g, col = nf * 32 + nw * 8 + t4 * 2;
            *(float2*)(red + row * 68 + col)       = make_float2(acc[mf][nf][0], acc[mf][nf][1]);
            *(float2*)(red + (row + 8) * 68 + col) = make_float2(acc[mf][nf][2], acc[mf][nf][3]);
        }
    __syncthreads();
    int lj = ej & 31;                                  // local col within CTA's 32
    float c0 = 0.f, c1 = 0.f, h0 = 0.f, h1 = 0.f;
    #pragma unroll
    for (int p = 0; p < 4; ++p) {
        const float* r = (const float*)(sm + SM_RED) + p * 2176 + er * 68;
        float2 pc = *(const float2*)(r + lj);
        float2 ph = *(const float2*)(r + 32 + lj);
        c0 += pc.x; c1 += pc.y; h0 += ph.x; h1 += ph.y;
    }
    float sp0 = bf16lo(hiw) + bf16lo(low);
    float sp1 = bf16hi(hiw) + bf16hi(low);
    float hv0 = (act == 0) ? tanhf(h0) : (act == 1) ? fmaxf(h0, 0.f) : (act == 2) ? sigf(h0) : h0;
    float hv1 = (act == 0) ? tanhf(h1) : (act == 1) ? fmaxf(h1, 0.f) : (act == 2) ? sigf(h1) : h1;
    float s0 = sp0 + sigf(c0) * (hv0 - sp0);
    float s1 = sp1 + sigf(c1) * (hv1 - sp1);
    if (do_mean) { mean[0] += s0; mean[1] += s1; }
    if (dst_pk) {
        __nv_bfloat16 b0 = __float2bfloat16(s0), b1 = __float2bfloat16(s1);
        uint32_t hw = ((uint32_t)__bfloat16_as_ushort(b1) << 16) | __bfloat16_as_ushort(b0);
        uint32_t lw = pack_bf16x2(s0 - __bfloat162float(b0), s1 - __bfloat162float(b1));
        char* dp = dst_pk + (ej >> 7) * A_IMG + er * 272 + (ej & 127) * 2;
        *(uint32_t*)dp = hw;
        *(uint32_t*)(dp + A_HALF) = lw;
    }
}

// ---- prepass: weights -> merged bf16 hi/lo tile images; hidden0 -> packed h state ----
__global__ void prepack_kernel(const float* __restrict__ W0, const float* __restrict__ Ws,
                               const float* __restrict__ hidden0) {
    const int lvl_order[8] = {0, 1, 2, 3, 4, 6, 5, 7};
    const int W_ITEMS = 640 * 1024;                    // tiles x (128 kr x 8 col-groups)
    const int TOTAL = W_ITEMS + 65536;                 // + 256 rows x 256 col-pairs of h0
    for (int idx = blockIdx.x * blockDim.x + threadIdx.x; idx < TOTAL; idx += gridDim.x * blockDim.x) {
        if (idx < W_ITEMS) {
            int g8 = idx & 7;
            int kr = (idx >> 3) & 127;
            int tt = idx >> 10;                        // 0..639
            int sp = tt >> 4, jb = tt & 15;
            const float* src; int kbase;
            if (sp < 8) { src = W0; kbase = sp * 128; }
            else { int sp2 = sp - 8; src = Ws + (size_t)lvl_order[sp2 >> 2] * 512 * 1024; kbase = (sp2 & 3) * 128; }
            __align__(16) __nv_bfloat16 hb[8], lb[8];
            #pragma unroll
            for (int e = 0; e < 8; ++e) {
                int cidx = g8 * 8 + e;
                int nw2 = cidx >> 4, w16 = cidx & 15;  // permuted: [c0..7 | h0..7] per n-warp
                int gc = (w16 < 8) ? (jb * 32 + nw2 * 8 + w16)
                                   : (512 + jb * 32 + nw2 * 8 + (w16 - 8));
                float wv = src[(size_t)(kbase + kr) * 1024 + gc];
                __nv_bfloat16 h = __float2bfloat16(wv);
                hb[e] = h;
                lb[e] = __float2bfloat16(wv - __bfloat162float(h));
            }
            size_t boff = (size_t)tt * B_IMG + kr * 144 + g8 * 16;
            *(uint4*)(g_Bpk + boff)          = *(const uint4*)hb;
            *(uint4*)(g_Bpk + boff + B_HALF) = *(const uint4*)lb;
        } else {
            int i2 = idx - W_ITEMS;
            int row = i2 >> 8, col = (i2 & 255) * 2;
            float v0 = hidden0[(size_t)row * NH + col];
            float v1 = hidden0[(size_t)row * NH + col + 1];
            __nv_bfloat16 b0 = __float2bfloat16(v0), b1 = __float2bfloat16(v1);
            uint32_t hw = ((uint32_t)__bfloat16_as_ushort(b1) << 16) | __bfloat16_as_ushort(b0);
            uint32_t lw = pack_bf16x2(v0 - __bfloat162float(b0), v1 - __bfloat162float(b1));
            char* dp = g_st + ((size_t)(5 * 8 + (row >> 5)) * 4 + (col >> 7)) * A_IMG
                     + (row & 31) * 272 + (col & 127) * 2;
            *(uint32_t*)dp = hw;
            *(uint32_t*)(dp + A_HALF) = lw;
        }
    }
}

__global__ void __launch_bounds__(NTHR, 1)
rnn_kernel(const float* __restrict__ inputs, float* __restrict__ out) {
    extern __shared__ char sm[];
    uint32_t smu = smem_u32(sm);
    int tid = threadIdx.x, lane = tid & 31, warp = tid >> 5;
    int kh = warp >> 2, nw = warp & 3;                 // 4 k-quarters x 4 n-warps
    int rb = blockIdx.x >> 4, jb = blockIdx.x & 15;
    int row_base = rb * 32, colc = jb * 32;
    int er = tid >> 4;                                 // 0..31 epilogue row
    int ej = colc + (tid & 15) * 2;                    // global col 0..510
    int grow = row_base + er;

    char* P[6];                                        // s0,s1,s2,s3,s5,h packed bases (this rb)
    #pragma unroll
    for (int s = 0; s < 6; ++s) P[s] = g_st + ((size_t)(s * 8 + rb) * 4) * A_IMG;

    if (tid == 0) {
        #pragma unroll
        for (int i = 0; i < 5; ++i) mbar_init(smu + SM_BAR + i * 8, 1);
    }
    __syncthreads();

    int n = 0, ua0 = 0, ua1 = 0, ap0 = 0, ap1 = 0;
    issue_B(0, jb, smu, tid);
    issue_B(1, jb, smu, tid);

    float acc[2][2][4];
    for (int t = 0; t < T_STEPS; ++t) {
        const float* x = inputs + (size_t)t * BATCH * NH;
        float mean[2] = {0.f, 0.f};

        // L0: s0 = highway(concat(x,h) @ W0); chunks 0-3 = x (STS), 4-7 = h (bulk)
        run_level(8, 4, x, P[5], sm, smu, tid, lane, kh, nw, row_base, jb, n, ua0, ua1, ap0, ap1, acc);
        red_epilogue(sm, acc, lane, kh, nw, tid, P[5], P[0], 0, false, mean, er, ej);
        grid_barrier(rb);
        // n1 = gate(s0 @ Ws0, tanh)
        run_level(4, 0, 0, P[0], sm, smu, tid, lane, kh, nw, row_base, jb, n, ua0, ua1, ap0, ap1, acc);
        red_epilogue(sm, acc, lane, kh, nw, tid, P[0], P[1], 0, true, mean, er, ej);
        grid_barrier(rb);
        // n2,n3,n4 (pred s1): relu, relu, identity
        run_level(4, 0, 0, P[1], sm, smu, tid, lane, kh, nw, row_base, jb, n, ua0, ua1, ap0, ap1, acc);
        red_epilogue(sm, acc, lane, kh, nw, tid, P[1], P[2], 1, true, mean, er, ej);
        run_level(4, 0, 0, P[1], sm, smu, tid, lane, kh, nw, row_base, jb, n, ua0, ua1, ap0, ap1, acc);
        red_epilogue(sm, acc, lane, kh, nw, tid, P[1], P[3], 1, true, mean, er, ej);
        run_level(4, 0, 0, P[1], sm, smu, tid, lane, kh, nw, row_base, jb, n, ua0, ua1, ap0, ap1, acc);
        red_epilogue(sm, acc, lane, kh, nw, tid, P[1], (char*)0, 3, true, mean, er, ej);
        grid_barrier(rb);
        // n5 = gate(s2 @ Ws4, tanh); n7 = gate(s3 @ Ws6, tanh)
        run_level(4, 0, 0, P[2], sm, smu, tid, lane, kh, nw, row_base, jb, n, ua0, ua1, ap0, ap1, acc);
        red_epilogue(sm, acc, lane, kh, nw, tid, P[2], P[4], 0, true, mean, er, ej);
        run_level(4, 0, 0, P[3], sm, smu, tid, lane, kh, nw, row_base, jb, n, ua0, ua1, ap0, ap1, acc);
        red_epilogue(sm, acc, lane, kh, nw, tid, P[3], (char*)0, 0, true, mean, er, ej);
        grid_barrier(rb);
        // n6 = gate(s5 @ Ws5, sigmoid); n8 = gate(s5 @ Ws7, relu)
        run_level(4, 0, 0, P[4], sm, smu, tid, lane, kh, nw, row_base, jb, n, ua0, ua1, ap0, ap1, acc);
        red_epilogue(sm, acc, lane, kh, nw, tid, P[4], (char*)0, 2, true, mean, er, ej);
        run_level(4, 0, 0, P[4], sm, smu, tid, lane, kh, nw, row_base, jb, n, ua0, ua1, ap0, ap1, acc);
        red_epilogue(sm, acc, lane, kh, nw, tid, P[4], (char*)0, 1, true, mean, er, ej);

        // finalize: h = mean(states 1..8); write packed h + fp32 out
        {
            float hv0 = mean[0] * 0.125f, hv1 = mean[1] * 0.125f;
            __nv_bfloat16 b0 = __float2bfloat16(hv0), b1 = __float2bfloat16(hv1);
            uint32_t hw = ((uint32_t)__bfloat16_as_ushort(b1) << 16) | __bfloat16_as_ushort(b0);
            uint32_t lw = pack_bf16x2(hv0 - __bfloat162float(b0), hv1 - __bfloat162float(b1));
            char* dp = P[5] + (ej >> 7) * A_IMG + er * 272 + (ej & 127) * 2;
            *(uint32_t*)dp = hw;
            *(uint32_t*)(dp + A_HALF) = lw;
            *(float2*)(out + ((size_t)t * BATCH + grow) * NH + ej) = make_float2(hv0, hv1);
            if (t == T_STEPS - 1)
                *(float2*)(out + (size_t)T_STEPS * BATCH * NH + (size_t)grow * NH + ej) = make_float2(hv0, hv1);
        }
        grid_barrier(rb);
    }
}

extern "C" void kernel_launch(void* const* d_in, const int* in_sizes, int n_in,
                              void* d_out, int out_size) {
    const float* inputs = (const float*)d_in[0];
    const float* hidden = (const float*)d_in[1];
    const float* W0     = (const float*)d_in[2];
    const float* Ws     = (const float*)d_in[3];
    float* out = (float*)d_out;

    prepack_kernel<<<704, 1024>>>(W0, Ws, hidden);
    cudaFuncSetAttribute(rnn_kernel, cudaFuncAttributeMaxDynamicSharedMemorySize, SM_TOTAL);
    rnn_kernel<<<NCTA, NTHR, SM_TOTAL>>>(inputs, out);
}

// round 12
// speedup vs baseline: 1.4407x; 1.0899x over previous
#include <cuda_runtime.h>
#include <cuda_bf16.h>
#include <math.h>
#include <stdint.h>

#define T_STEPS 400
#define BATCH   256
#define NH      512
#define NCTA    128
#define NTHR    512
#define TOT_CHUNKS (T_STEPS*40)

// ---- tile images ----
#define A_IMG   17408                 // 32 rows x 272B (hi 8704) + lo 8704
#define A_HALF  8704
#define B_IMG   36864                 // 128 rows x 144B (hi 18432) + lo 18432
#define B_HALF  18432

// ---- smem layout (bytes) ----
#define SM_B0   0                     // 3 rotating B slots (full/empty mbar piped)
#define SM_A    110592                // 4 chunk positions = one level's A (69632)
#define SM_RED  180224                // 4 x 8704 partials
#define SM_BAR  215040                // Bf[3], Be[3], Af, Ae (8B each)
#define SM_TOTAL 215168

#define BAR_BF(s) (SM_BAR + (s)*8)
#define BAR_BE(s) (SM_BAR + 24 + (s)*8)
#define BAR_AF    (SM_BAR + 48)
#define BAR_AE    (SM_BAR + 56)

// ---- persistent device buffers (no cudaMalloc allowed) ----
__device__ __align__(16) char g_Bpk[640ull*B_IMG];          // 40 sched-slots x 16 jb
__device__ __align__(16) char g_st[6ull*8*4*A_IMG];         // states s0,s1,s2,s3,s5,h : [st][rb][chunk]
__device__ unsigned long long g_barr[8*32];                 // rb-local barrier counters (monotonic)

// ---- asm helpers ----
__device__ __forceinline__ uint32_t smem_u32(const void* p) {
    uint32_t a;
    asm("{ .reg .u64 t; cvta.to.shared.u64 t, %1; cvt.u32.u64 %0, t; }" : "=r"(a) : "l"(p));
    return a;
}
#define LDM4(r, a) \
    asm volatile("ldmatrix.sync.aligned.m8n8.x4.shared.b16 {%0,%1,%2,%3}, [%4];" \
        : "=r"((r)[0]), "=r"((r)[1]), "=r"((r)[2]), "=r"((r)[3]) : "r"(a))
#define LDM4T(r, a) \
    asm volatile("ldmatrix.sync.aligned.m8n8.x4.trans.shared.b16 {%0,%1,%2,%3}, [%4];" \
        : "=r"((r)[0]), "=r"((r)[1]), "=r"((r)[2]), "=r"((r)[3]) : "r"(a))
#define MMAB(d, a, b0, b1) \
    asm volatile("mma.sync.aligned.m16n8k16.row.col.f32.bf16.bf16.f32 " \
        "{%0,%1,%2,%3},{%4,%5,%6,%7},{%8,%9},{%0,%1,%2,%3};" \
        : "+f"((d)[0]), "+f"((d)[1]), "+f"((d)[2]), "+f"((d)[3]) \
        : "r"((a)[0]), "r"((a)[1]), "r"((a)[2]), "r"((a)[3]), "r"(b0), "r"(b1))
#define MBAR_ARRIVE(bar) \
    asm volatile("mbarrier.arrive.shared.b64 _, [%0];" :: "r"(bar) : "memory")

__device__ __forceinline__ void mbar_init(uint32_t bar, uint32_t cnt) {
    asm volatile("mbarrier.init.shared.b64 [%0], %1;" :: "r"(bar), "r"(cnt) : "memory");
}
__device__ __forceinline__ void mbar_wait(uint32_t bar, uint32_t parity) {
    asm volatile(
        "{\n\t.reg .pred P;\n\tWL_%=:\n\t"
        "mbarrier.try_wait.parity.acquire.cta.shared::cta.b64 P, [%0], %1;\n\t"
        "@P bra.uni WD_%=;\n\tbra.uni WL_%=;\n\tWD_%=:\n\t}"
        :: "r"(bar), "r"(parity) : "memory");
}
__device__ __forceinline__ void bulk_g2s(uint32_t dst, const void* src, uint32_t bytes, uint32_t bar) {
    asm volatile("mbarrier.arrive.expect_tx.shared.b64 _, [%0], %1;" :: "r"(bar), "r"(bytes) : "memory");
    asm volatile("cp.async.bulk.shared::cta.global.mbarrier::complete_tx::bytes [%0], [%1], %2, [%3];"
                 :: "r"(dst), "l"(src), "r"(bytes), "r"(bar) : "memory");
}

__device__ __forceinline__ void grid_barrier(int rb) {
    __syncthreads();
    if (threadIdx.x == 0) {
        __threadfence();
        unsigned long long* ctr = &g_barr[rb * 32];
        unsigned long long arr = atomicAdd(ctr, 1ULL);
        unsigned long long target = (arr / 16 + 1ULL) * 16;
        while (*(volatile unsigned long long*)ctr < target) { __nanosleep(32); }
        __threadfence();
    }
    __syncthreads();
}

__device__ __forceinline__ float sigf(float x) { return 1.0f / (1.0f + expf(-x)); }
__device__ __forceinline__ uint32_t pack_bf16x2(float a, float b) {
    __nv_bfloat16 ba = __float2bfloat16(a), bb = __float2bfloat16(b);
    return ((uint32_t)__bfloat16_as_ushort(bb) << 16) | __bfloat16_as_ushort(ba);
}
__device__ __forceinline__ float bf16lo(uint32_t w) {
    return __bfloat162float(__ushort_as_bfloat16((unsigned short)(w & 0xffff)));
}
__device__ __forceinline__ float bf16hi(uint32_t w) {
    return __bfloat162float(__ushort_as_bfloat16((unsigned short)(w >> 16)));
}

// Producer: issue B tile q into slot q%3 after the slot's previous readers released it.
__device__ __forceinline__ void issue_B(int q, int jb, uint32_t smu) {
    if (q >= TOT_CHUNKS) return;
    mbar_wait(smu + BAR_BE(q % 3), (uint32_t)(((q / 3) & 1) ^ 1));
    bulk_g2s(smu + SM_B0 + (q % 3) * B_IMG,
             g_Bpk + ((size_t)((q % 40) * 16 + jb)) * B_IMG, B_IMG, smu + BAR_BF(q % 3));
}

// Producer: one bulk for a whole level's A (4 chunk images, 69632 B).
__device__ __forceinline__ void a_bulk(const char* src, uint32_t smu, int nae) {
    mbar_wait(smu + BAR_AE, (uint32_t)((nae & 1) ^ 1));
    asm volatile("fence.proxy.async.shared::cta;" ::: "memory");
    bulk_g2s(smu + SM_A, src, 4 * A_IMG, smu + BAR_AF);
}

// x prestage: 4 chunks of fp32 -> regs; later converted+stored to the A region.
__device__ __forceinline__ void x_load(float4 xp[8], const float* __restrict__ x,
                                       int row_base, int tid) {
    #pragma unroll
    for (int it = 0; it < 8; ++it) {
        int idx = tid + it * NTHR;                 // 0..4095
        int ch = idx >> 10, r = (idx >> 5) & 31, k4 = idx & 31;
        xp[it] = *(const float4*)(x + (size_t)(row_base + r) * NH + ch * 128 + k4 * 4);
    }
}
__device__ __forceinline__ void x_store(const float4 xp[8], char* sm, int tid) {
    #pragma unroll
    for (int it = 0; it < 8; ++it) {
        int idx = tid + it * NTHR;
        int ch = idx >> 10, r = (idx >> 5) & 31, k4 = idx & 31;
        float4 v = xp[it];
        __nv_bfloat16 h0 = __float2bfloat16(v.x), h1 = __float2bfloat16(v.y),
                      h2 = __float2bfloat16(v.z), h3 = __float2bfloat16(v.w);
        uint32_t ph0 = ((uint32_t)__bfloat16_as_ushort(h1) << 16) | __bfloat16_as_ushort(h0);
        uint32_t ph1 = ((uint32_t)__bfloat16_as_ushort(h3) << 16) | __bfloat16_as_ushort(h2);
        uint32_t pl0 = pack_bf16x2(v.x - __bfloat162float(h0), v.y - __bfloat162float(h1));
        uint32_t pl1 = pack_bf16x2(v.z - __bfloat162float(h2), v.w - __bfloat162float(h3));
        char* ab = sm + SM_A + ch * A_IMG + r * 272 + k4 * 8;
        *(uint2*)ab            = make_uint2(ph0, ph1);
        *(uint2*)(ab + A_HALF) = make_uint2(pl0, pl1);
    }
}

// One K=128 chunk of HMMA. Warp (kh,nw): ks = kh*2+{0,1}; n cols {nw*8 (c), 32+nw*8 (h)}.
__device__ __forceinline__ void mma_chunk(uint32_t smu, int slot, int abuf_off,
                                          int lane, int kh, int nw, float acc[2][2][4]) {
    uint32_t Bb = smu + SM_B0 + slot * B_IMG;
    uint32_t Ab = smu + SM_A + abuf_off;
    int l15 = lane & 15, l16 = lane >> 4;
    #pragma unroll
    for (int ksl = 0; ksl < 2; ++ksl) {
        int ks = kh * 2 + ksl;
        uint32_t ah[2][4], al[2][4], bh[4], bl[4];
        uint32_t kb = (uint32_t)(ks * 16 + l16 * 8) * 2;
        #pragma unroll
        for (int mf = 0; mf < 2; ++mf) {
            uint32_t aa = Ab + (uint32_t)(mf * 16 + l15) * 272 + kb;
            LDM4(ah[mf], aa);
            LDM4(al[mf], aa + A_HALF);
        }
        uint32_t ba = Bb + (uint32_t)(ks * 16 + l15) * 144 + (uint32_t)(nw * 32 + l16 * 16);
        LDM4T(bh, ba);
        LDM4T(bl, ba + B_HALF);
        #pragma unroll
        for (int mf = 0; mf < 2; ++mf) {
            MMAB(acc[mf][0], ah[mf], bh[0], bh[1]);
            MMAB(acc[mf][0], ah[mf], bl[0], bl[1]);
            MMAB(acc[mf][0], al[mf], bh[0], bh[1]);
            MMAB(acc[mf][1], ah[mf], bh[2], bh[3]);
            MMAB(acc[mf][1], ah[mf], bl[2], bl[3]);
            MMAB(acc[mf][1], al[mf], bh[2], bh[3]);
        }
    }
}

// 4 chunks, NO CTA barrier: Bf wait -> mma -> Be arrive -> prefetch B(n+2).
__device__ __forceinline__ void chunks4(uint32_t smu, int lane, int tid, int kh, int nw,
                                        int jb, int& n, float acc[2][2][4]) {
    #pragma unroll
    for (int c = 0; c < 4; ++c) {
        mbar_wait(smu + BAR_BF(n % 3), (uint32_t)((n / 3) & 1));
        mma_chunk(smu, n % 3, c * A_IMG, lane, kh, nw, acc);
        if (lane == 0) MBAR_ARRIVE(smu + BAR_BE(n % 3));
        if (tid == 0) issue_B(n + 2, jb, smu);
        ++n;
    }
}
#define ZERO_ACC(acc) { _Pragma("unroll") for (int _m = 0; _m < 2; ++_m) \
    _Pragma("unroll") for (int _f = 0; _f < 2; ++_f) \
    _Pragma("unroll") for (int _e = 0; _e < 4; ++_e) (acc)[_m][_f][_e] = 0.f; }

// Reduce 4 k-partials, gate vs sp (read from the resident smem A image), store packed state.
// sp is reconstructed (consuming the LDS values) BEFORE the AE arrive, so the A region
// can never be overwritten while the loads are in flight.
__device__ void red_epilogue(char* sm, uint32_t smu, const float acc[2][2][4], int lane,
                             int kh, int nw, int tid, char* dst_pk, int act, bool do_mean,
                             float mean[2], int er, int ej, bool arrive_ae) {
    const char* spp = sm + SM_A + (ej >> 7) * A_IMG + er * 272 + (ej & 127) * 2;
    uint32_t hiw = *(const uint32_t*)spp;
    uint32_t low = *(const uint32_t*)(spp + A_HALF);
    float sp0 = bf16lo(hiw) + bf16lo(low);             // consume loads (forces completion)
    float sp1 = bf16hi(hiw) + bf16hi(low);
    if (arrive_ae) {                                   // release A region early (post-consume)
        __syncwarp();
        if (lane == 0) MBAR_ARRIVE(smu + BAR_AE);
    }
    __syncthreads();                                   // all mma done; red buffer free
    float* red = (float*)(sm + SM_RED) + kh * 2176;    // 32 x 68
    int g = lane >> 2, t4 = lane & 3;
    #pragma unroll
    for (int mf = 0; mf < 2; ++mf)
        #pragma unroll
        for (int nf = 0; nf < 2; ++nf) {
            int row = mf * 16 + g, col = nf * 32 + nw * 8 + t4 * 2;
            *(float2*)(red + row * 68 + col)       = make_float2(acc[mf][nf][0], acc[mf][nf][1]);
            *(float2*)(red + (row + 8) * 68 + col) = make_float2(acc[mf][nf][2], acc[mf][nf][3]);
        }
    __syncthreads();
    int lj = ej & 31;
    float c0 = 0.f, c1 = 0.f, h0 = 0.f, h1 = 0.f;
    #pragma unroll
    for (int p = 0; p < 4; ++p) {
        const float* r = (const float*)(sm + SM_RED) + p * 2176 + er * 68;
        float2 pc = *(const float2*)(r + lj);
        float2 ph = *(const float2*)(r + 32 + lj);
        c0 += pc.x; c1 += pc.y; h0 += ph.x; h1 += ph.y;
    }
    float hv0 = (act == 0) ? tanhf(h0) : (act == 1) ? fmaxf(h0, 0.f) : (act == 2) ? sigf(h0) : h0;
    float hv1 = (act == 0) ? tanhf(h1) : (act == 1) ? fmaxf(h1, 0.f) : (act == 2) ? sigf(h1) : h1;
    float s0 = sp0 + sigf(c0) * (hv0 - sp0);
    float s1 = sp1 + sigf(c1) * (hv1 - sp1);
    if (do_mean) { mean[0] += s0; mean[1] += s1; }
    if (dst_pk) {
        __nv_bfloat16 b0 = __float2bfloat16(s0), b1 = __float2bfloat16(s1);
        uint32_t hw = ((uint32_t)__bfloat16_as_ushort(b1) << 16) | __bfloat16_as_ushort(b0);
        uint32_t lw = pack_bf16x2(s0 - __bfloat162float(b0), s1 - __bfloat162float(b1));
        char* dp = dst_pk + (ej >> 7) * A_IMG + er * 272 + (ej & 127) * 2;
        *(uint32_t*)dp = hw;
        *(uint32_t*)(dp + A_HALF) = lw;
    }
}

// ---- prepass: weights -> merged bf16 hi/lo tile images; hidden0 -> packed h state ----
__global__ void prepack_kernel(const float* __restrict__ W0, const float* __restrict__ Ws,
                               const float* __restrict__ hidden0) {
    const int lvl_order[8] = {0, 1, 2, 3, 4, 6, 5, 7};
    const int W_ITEMS = 640 * 1024;
    const int TOTAL = W_ITEMS + 65536;
    for (int idx = blockIdx.x * blockDim.x + threadIdx.x; idx < TOTAL; idx += gridDim.x * blockDim.x) {
        if (idx < W_ITEMS) {
            int g8 = idx & 7;
            int kr = (idx >> 3) & 127;
            int tt = idx >> 10;
            int sp = tt >> 4, jb = tt & 15;
            const float* src; int kbase;
            if (sp < 8) { src = W0; kbase = sp * 128; }
            else { int sp2 = sp - 8; src = Ws + (size_t)lvl_order[sp2 >> 2] * 512 * 1024; kbase = (sp2 & 3) * 128; }
            __align__(16) __nv_bfloat16 hb[8], lb[8];
            #pragma unroll
            for (int e = 0; e < 8; ++e) {
                int cidx = g8 * 8 + e;
                int nw2 = cidx >> 4, w16 = cidx & 15;
                int gc = (w16 < 8) ? (jb * 32 + nw2 * 8 + w16)
                                   : (512 + jb * 32 + nw2 * 8 + (w16 - 8));
                float wv = src[(size_t)(kbase + kr) * 1024 + gc];
                __nv_bfloat16 h = __float2bfloat16(wv);
                hb[e] = h;
                lb[e] = __float2bfloat16(wv - __bfloat162float(h));
            }
            size_t boff = (size_t)tt * B_IMG + kr * 144 + g8 * 16;
            *(uint4*)(g_Bpk + boff)          = *(const uint4*)hb;
            *(uint4*)(g_Bpk + boff + B_HALF) = *(const uint4*)lb;
        } else {
            int i2 = idx - W_ITEMS;
            int row = i2 >> 8, col = (i2 & 255) * 2;
            float v0 = hidden0[(size_t)row * NH + col];
            float v1 = hidden0[(size_t)row * NH + col + 1];
            __nv_bfloat16 b0 = __float2bfloat16(v0), b1 = __float2bfloat16(v1);
            uint32_t hw = ((uint32_t)__bfloat16_as_ushort(b1) << 16) | __bfloat16_as_ushort(b0);
            uint32_t lw = pack_bf16x2(v0 - __bfloat162float(b0), v1 - __bfloat162float(b1));
            char* dp = g_st + ((size_t)(5 * 8 + (row >> 5)) * 4 + (col >> 7)) * A_IMG
                     + (row & 31) * 272 + (col & 127) * 2;
            *(uint32_t*)dp = hw;
            *(uint32_t*)(dp + A_HALF) = lw;
        }
    }
}

__global__ void __launch_bounds__(NTHR, 1)
rnn_kernel(const float* __restrict__ inputs, float* __restrict__ out) {
    extern __shared__ char sm[];
    uint32_t smu = smem_u32(sm);
    int tid = threadIdx.x, lane = tid & 31, warp = tid >> 5;
    int kh = warp >> 2, nw = warp & 3;
    int rb = blockIdx.x >> 4, jb = blockIdx.x & 15;
    int row_base = rb * 32, colc = jb * 32;
    int er = tid >> 4;
    int ej = colc + (tid & 15) * 2;
    int grow = row_base + er;

    char* P[6];
    #pragma unroll
    for (int s = 0; s < 6; ++s) P[s] = g_st + ((size_t)(s * 8 + rb) * 4) * A_IMG;

    if (tid == 0) {
        #pragma unroll
        for (int s = 0; s < 3; ++s) { mbar_init(smu + BAR_BF(s), 1); mbar_init(smu + BAR_BE(s), 16); }
        mbar_init(smu + BAR_AF, 1);
        mbar_init(smu + BAR_AE, 16);
    }
    __syncthreads();

    int n = 0, naf = 0, nae = 0;
    if (tid == 0) { issue_B(0, jb, smu); issue_B(1, jb, smu); }

    float4 xp[8];
    x_load(xp, inputs, row_base, tid);

    float acc[2][2][4];
    for (int t = 0; t < T_STEPS; ++t) {
        float mean[2] = {0.f, 0.f};

        // ---- L0: s0 = highway(concat(x,h) @ W0) ----
        x_store(xp, sm, tid);                       // wave1 A = x (positions 0-3)
        __syncthreads();
        ZERO_ACC(acc);
        chunks4(smu, lane, tid, kh, nw, jb, n, acc);
        __syncthreads();                            // wave1 mma done by all
        if (tid == 0) a_bulk(P[5], smu, nae);       // wave2 A = h
        mbar_wait(smu + BAR_AF, (uint32_t)(naf & 1)); ++naf;
        chunks4(smu, lane, tid, kh, nw, jb, n, acc);
        red_epilogue(sm, smu, acc, lane, kh, nw, tid, P[0], 0, false, mean, er, ej, true); ++nae;
        grid_barrier(rb);

        // ---- n1 = gate(s0 @ Ws0, tanh) ----
        if (tid == 0) a_bulk(P[0], smu, nae);
        mbar_wait(smu + BAR_AF, (uint32_t)(naf & 1)); ++naf;
        ZERO_ACC(acc);
        chunks4(smu, lane, tid, kh, nw, jb, n, acc);
        red_epilogue(sm, smu, acc, lane, kh, nw, tid, P[1], 0, true, mean, er, ej, true); ++nae;
        grid_barrier(rb);

        // ---- n2,n3,n4 (pred s1 -> A loaded once, reused) ----
        if (tid == 0) a_bulk(P[1], smu, nae);
        mbar_wait(smu + BAR_AF, (uint32_t)(naf & 1)); ++naf;
        ZERO_ACC(acc);
        chunks4(smu, lane, tid, kh, nw, jb, n, acc);
        red_epilogue(sm, smu, acc, lane, kh, nw, tid, P[2], 1, true, mean, er, ej, false);
        ZERO_ACC(acc);
        chunks4(smu, lane, tid, kh, nw, jb, n, acc);
        red_epilogue(sm, smu, acc, lane, kh, nw, tid, P[3], 1, true, mean, er, ej, false);
        ZERO_ACC(acc);
        chunks4(smu, lane, tid, kh, nw, jb, n, acc);
        red_epilogue(sm, smu, acc, lane, kh, nw, tid, (char*)0, 3, true, mean, er, ej, true); ++nae;
        grid_barrier(rb);

        // ---- n5 = gate(s2 @ Ws4, tanh); n7 = gate(s3 @ Ws6, tanh) ----
        if (tid == 0) a_bulk(P[2], smu, nae);
        mbar_wait(smu + BAR_AF, (uint32_t)(naf & 1)); ++naf;
        ZERO_ACC(acc);
        chunks4(smu, lane, tid, kh, nw, jb, n, acc);
        red_epilogue(sm, smu, acc, lane, kh, nw, tid, P[4], 0, true, mean, er, ej, true); ++nae;
        if (tid == 0) a_bulk(P[3], smu, nae);
        mbar_wait(smu + BAR_AF, (uint32_t)(naf & 1)); ++naf;
        ZERO_ACC(acc);
        chunks4(smu, lane, tid, kh, nw, jb, n, acc);
        red_epilogue(sm, smu, acc, lane, kh, nw, tid, (char*)0, 0, true, mean, er, ej, true); ++nae;
        grid_barrier(rb);

        // ---- n6 = gate(s5 @ Ws5, sigmoid); n8 = gate(s5 @ Ws7, relu) (s5 reused) ----
        if (tid == 0) a_bulk(P[4], smu, nae);
        mbar_wait(smu + BAR_AF, (uint32_t)(naf & 1)); ++naf;
        ZERO_ACC(acc);
        chunks4(smu, lane, tid, kh, nw, jb, n, acc);
        red_epilogue(sm, smu, acc, lane, kh, nw, tid, (char*)0, 2, true, mean, er, ej, false);
        ZERO_ACC(acc);
        chunks4(smu, lane, tid, kh, nw, jb, n, acc);
        red_epilogue(sm, smu, acc, lane, kh, nw, tid, (char*)0, 1, true, mean, er, ej, true); ++nae;

        // preload next step's x while waiting on the final barrier
        if (t + 1 < T_STEPS) x_load(xp, inputs + (size_t)(t + 1) * BATCH * NH, row_base, tid);

        // ---- finalize: h = mean(states 1..8); packed h + fp32 out ----
        {
            float hv0 = mean[0] * 0.125f, hv1 = mean[1] * 0.125f;
            __nv_bfloat16 b0 = __float2bfloat16(hv0), b1 = __float2bfloat16(hv1);
            uint32_t hw = ((uint32_t)__bfloat16_as_ushort(b1) << 16) | __bfloat16_as_ushort(b0);
            uint32_t lw = pack_bf16x2(hv0 - __bfloat162float(b0), hv1 - __bfloat162float(b1));
            char* dp = P[5] + (ej >> 7) * A_IMG + er * 272 + (ej & 127) * 2;
            *(uint32_t*)dp = hw;
            *(uint32_t*)(dp + A_HALF) = lw;
            *(float2*)(out + ((size_t)t * BATCH + grow) * NH + ej) = make_float2(hv0, hv1);
            if (t == T_STEPS - 1)
                *(float2*)(out + (size_t)T_STEPS * BATCH * NH + (size_t)grow * NH + ej) = make_float2(hv0, hv1);
        }
        grid_barrier(rb);
    }
}

extern "C" void kernel_launch(void* const* d_in, const int* in_sizes, int n_in,
                              void* d_out, int out_size) {
    const float* inputs = (const float*)d_in[0];
    const float* hidden = (const float*)d_in[1];
    const float* W0     = (const float*)d_in[2];
    const float* Ws     = (const float*)d_in[3];
    float* out = (float*)d_out;

    prepack_kernel<<<704, 1024>>>(W0, Ws, hidden);
    cudaFuncSetAttribute(rnn_kernel, cudaFuncAttributeMaxDynamicSharedMemorySize, SM_TOTAL);
    rnn_kernel<<<NCTA, NTHR, SM_TOTAL>>>(inputs, out);
}

// round 13
// speedup vs baseline: 1.5306x; 1.0624x over previous
#include <cuda_runtime.h>
#include <cuda_bf16.h>
#include <math.h>
#include <stdint.h>

#define T_STEPS 400
#define BATCH   256
#define NH      512
#define NCTA    128
#define NTHR    512
#define TOT_CHUNKS (T_STEPS*40)

// ---- tile images ----
#define A_IMG   17408                 // 32 rows x 272B (hi 8704) + lo 8704
#define A_HALF  8704
#define B_IMG   36864                 // 128 rows x 144B (hi 18432) + lo 18432
#define B_HALF  18432

// ---- smem layout (bytes) ----
#define SM_B0   0                     // 3 rotating B slots (full/empty mbar piped)
#define SM_A    110592                // 4 chunk positions = one level's A (69632)
#define SM_RED  180224                // 4 x 8704 partials
#define SM_BAR  215040                // Bf[3], Be[3], AF[4], AE
#define SM_TOTAL 215168

#define BAR_BF(s) (SM_BAR + (s)*8)
#define BAR_BE(s) (SM_BAR + 24 + (s)*8)
#define BAR_AF(c) (SM_BAR + 48 + (c)*8)
#define BAR_AE    (SM_BAR + 80)

// ---- persistent device buffers (no cudaMalloc allowed) ----
__device__ __align__(16) char g_Bpk[640ull*B_IMG];          // 40 sched-slots x 16 jb
__device__ __align__(16) char g_st [6ull*8*4*A_IMG];        // states s0,s1,s2,s3,s5,h : [st][rb][chunk]
__device__ __align__(16) char g_xpk[(size_t)T_STEPS*8*4*A_IMG];  // prepacked x images [t][rb][chunk]
__device__ unsigned long long g_barr[8*32];                 // rb-local barrier counters (monotonic)

// ---- asm helpers ----
__device__ __forceinline__ uint32_t smem_u32(const void* p) {
    uint32_t a;
    asm("{ .reg .u64 t; cvta.to.shared.u64 t, %1; cvt.u32.u64 %0, t; }" : "=r"(a) : "l"(p));
    return a;
}
#define LDM4(r, a) \
    asm volatile("ldmatrix.sync.aligned.m8n8.x4.shared.b16 {%0,%1,%2,%3}, [%4];" \
        : "=r"((r)[0]), "=r"((r)[1]), "=r"((r)[2]), "=r"((r)[3]) : "r"(a))
#define LDM4T(r, a) \
    asm volatile("ldmatrix.sync.aligned.m8n8.x4.trans.shared.b16 {%0,%1,%2,%3}, [%4];" \
        : "=r"((r)[0]), "=r"((r)[1]), "=r"((r)[2]), "=r"((r)[3]) : "r"(a))
#define MMAB(d, a, b0, b1) \
    asm volatile("mma.sync.aligned.m16n8k16.row.col.f32.bf16.bf16.f32 " \
        "{%0,%1,%2,%3},{%4,%5,%6,%7},{%8,%9},{%0,%1,%2,%3};" \
        : "+f"((d)[0]), "+f"((d)[1]), "+f"((d)[2]), "+f"((d)[3]) \
        : "r"((a)[0]), "r"((a)[1]), "r"((a)[2]), "r"((a)[3]), "r"(b0), "r"(b1))
#define MBAR_ARRIVE(bar) \
    asm volatile("mbarrier.arrive.shared.b64 _, [%0];" :: "r"(bar) : "memory")

__device__ __forceinline__ void mbar_init(uint32_t bar, uint32_t cnt) {
    asm volatile("mbarrier.init.shared.b64 [%0], %1;" :: "r"(bar), "r"(cnt) : "memory");
}
__device__ __forceinline__ void mbar_wait(uint32_t bar, uint32_t parity) {
    asm volatile(
        "{\n\t.reg .pred P;\n\tWL_%=:\n\t"
        "mbarrier.try_wait.parity.acquire.cta.shared::cta.b64 P, [%0], %1;\n\t"
        "@P bra.uni WD_%=;\n\tbra.uni WL_%=;\n\tWD_%=:\n\t}"
        :: "r"(bar), "r"(parity) : "memory");
}
__device__ __forceinline__ void bulk_g2s(uint32_t dst, const void* src, uint32_t bytes, uint32_t bar) {
    asm volatile("mbarrier.arrive.expect_tx.shared.b64 _, [%0], %1;" :: "r"(bar), "r"(bytes) : "memory");
    asm volatile("cp.async.bulk.shared::cta.global.mbarrier::complete_tx::bytes [%0], [%1], %2, [%3];"
                 :: "r"(dst), "l"(src), "r"(bytes), "r"(bar) : "memory");
}

__device__ __forceinline__ void grid_barrier(int rb) {
    __syncthreads();
    if (threadIdx.x == 0) {
        __threadfence();
        unsigned long long* ctr = &g_barr[rb * 32];
        unsigned long long arr = atomicAdd(ctr, 1ULL);
        unsigned long long target = (arr / 16 + 1ULL) * 16;
        while (*(volatile unsigned long long*)ctr < target) { __nanosleep(32); }
        __threadfence();
    }
    __syncthreads();
}

__device__ __forceinline__ float sigf(float x) { return 1.0f / (1.0f + expf(-x)); }
__device__ __forceinline__ uint32_t pack_bf16x2(float a, float b) {
    __nv_bfloat16 ba = __float2bfloat16(a), bb = __float2bfloat16(b);
    return ((uint32_t)__bfloat16_as_ushort(bb) << 16) | __bfloat16_as_ushort(ba);
}
__device__ __forceinline__ float bf16lo(uint32_t w) {
    return __bfloat162float(__ushort_as_bfloat16((unsigned short)(w & 0xffff)));
}
__device__ __forceinline__ float bf16hi(uint32_t w) {
    return __bfloat162float(__ushort_as_bfloat16((unsigned short)(w >> 16)));
}

// Producer: issue B tile q into slot q%3 after the slot's previous readers released it.
__device__ __forceinline__ void issue_B(int q, int jb, uint32_t smu) {
    if (q >= TOT_CHUNKS) return;
    mbar_wait(smu + BAR_BE(q % 3), (uint32_t)(((q / 3) & 1) ^ 1));
    bulk_g2s(smu + SM_B0 + (q % 3) * B_IMG,
             g_Bpk + ((size_t)((q % 40) * 16 + jb)) * B_IMG, B_IMG, smu + BAR_BF(q % 3));
}

// Producer: one level's A as 4 per-chunk bulks (chunk c -> AF[c]).
// Called by tid0 only; waits the AE epoch (region free) once.
__device__ __forceinline__ void a_bulk4(const char* src, uint32_t smu, int nae) {
    mbar_wait(smu + BAR_AE, (uint32_t)((nae & 1) ^ 1));
    asm volatile("fence.proxy.async.shared::cta;" ::: "memory");
    #pragma unroll
    for (int c = 0; c < 4; ++c)
        bulk_g2s(smu + SM_A + c * A_IMG, src + (size_t)c * A_IMG, A_IMG, smu + BAR_AF(c));
}

// One K=128 chunk of HMMA. Warp (kh,nw): ks = kh*2+{0,1}; n cols {nw*8 (c), 32+nw*8 (h)}.
__device__ __forceinline__ void mma_chunk(uint32_t smu, int slot, int abuf_off,
                                          int lane, int kh, int nw, float acc[2][2][4]) {
    uint32_t Bb = smu + SM_B0 + slot * B_IMG;
    uint32_t Ab = smu + SM_A + abuf_off;
    int l15 = lane & 15, l16 = lane >> 4;
    #pragma unroll
    for (int ksl = 0; ksl < 2; ++ksl) {
        int ks = kh * 2 + ksl;
        uint32_t ah[2][4], al[2][4], bh[4], bl[4];
        uint32_t kb = (uint32_t)(ks * 16 + l16 * 8) * 2;
        #pragma unroll
        for (int mf = 0; mf < 2; ++mf) {
            uint32_t aa = Ab + (uint32_t)(mf * 16 + l15) * 272 + kb;
            LDM4(ah[mf], aa);
            LDM4(al[mf], aa + A_HALF);
        }
        uint32_t ba = Bb + (uint32_t)(ks * 16 + l15) * 144 + (uint32_t)(nw * 32 + l16 * 16);
        LDM4T(bh, ba);
        LDM4T(bl, ba + B_HALF);
        #pragma unroll
        for (int mf = 0; mf < 2; ++mf) {
            MMAB(acc[mf][0], ah[mf], bh[0], bh[1]);
            MMAB(acc[mf][0], ah[mf], bl[0], bl[1]);
            MMAB(acc[mf][0], al[mf], bh[0], bh[1]);
            MMAB(acc[mf][1], ah[mf], bh[2], bh[3]);
            MMAB(acc[mf][1], ah[mf], bl[2], bl[3]);
            MMAB(acc[mf][1], al[mf], bh[2], bh[3]);
        }
    }
}

// 4 chunks, NO CTA barrier. Optional per-chunk AF wait (fresh A load); afp = parity of
// the latest a_bulk4 call. Bf wait -> mma -> Be arrive -> prefetch B(n+2).
__device__ __forceinline__ void chunks4(uint32_t smu, int lane, int tid, int kh, int nw,
                                        int jb, int& n, float acc[2][2][4],
                                        bool af, uint32_t afp) {
    #pragma unroll
    for (int c = 0; c < 4; ++c) {
        if (af) mbar_wait(smu + BAR_AF(c), afp);
        mbar_wait(smu + BAR_BF(n % 3), (uint32_t)((n / 3) & 1));
        mma_chunk(smu, n % 3, c * A_IMG, lane, kh, nw, acc);
        if (lane == 0) MBAR_ARRIVE(smu + BAR_BE(n % 3));
        if (tid == 0) issue_B(n + 2, jb, smu);
        ++n;
    }
}
#define ZERO_ACC(acc) { _Pragma("unroll") for (int _m = 0; _m < 2; ++_m) \
    _Pragma("unroll") for (int _f = 0; _f < 2; ++_f) \
    _Pragma("unroll") for (int _e = 0; _e < 4; ++_e) (acc)[_m][_f][_e] = 0.f; }

// Reduce 4 k-partials, gate vs sp (read from the resident smem A image), store packed state.
// sp is consumed BEFORE the AE arrive so the region can't be overwritten mid-read.
__device__ void red_epilogue(char* sm, uint32_t smu, const float acc[2][2][4], int lane,
                             int kh, int nw, int tid, char* dst_pk, int act, bool do_mean,
                             float mean[2], int er, int ej, bool arrive_ae) {
    const char* spp = sm + SM_A + (ej >> 7) * A_IMG + er * 272 + (ej & 127) * 2;
    uint32_t hiw = *(const uint32_t*)spp;
    uint32_t low = *(const uint32_t*)(spp + A_HALF);
    float sp0 = bf16lo(hiw) + bf16lo(low);
    float sp1 = bf16hi(hiw) + bf16hi(low);
    if (arrive_ae) {
        __syncwarp();
        if (lane == 0) MBAR_ARRIVE(smu + BAR_AE);
    }
    __syncthreads();                                   // all mma done; red buffer free
    float* red = (float*)(sm + SM_RED) + kh * 2176;    // 32 x 68
    int g = lane >> 2, t4 = lane & 3;
    #pragma unroll
    for (int mf = 0; mf < 2; ++mf)
        #pragma unroll
        for (int nf = 0; nf < 2; ++nf) {
            int row = mf * 16 + g, col = nf * 32 + nw * 8 + t4 * 2;
            *(float2*)(red + row * 68 + col)       = make_float2(acc[mf][nf][0], acc[mf][nf][1]);
            *(float2*)(red + (row + 8) * 68 + col) = make_float2(acc[mf][nf][2], acc[mf][nf][3]);
        }
    __syncthreads();
    int lj = ej & 31;
    float c0 = 0.f, c1 = 0.f, h0 = 0.f, h1 = 0.f;
    #pragma unroll
    for (int p = 0; p < 4; ++p) {
        const float* r = (const float*)(sm + SM_RED) + p * 2176 + er * 68;
        float2 pc = *(const float2*)(r + lj);
        float2 ph = *(const float2*)(r + 32 + lj);
        c0 += pc.x; c1 += pc.y; h0 += ph.x; h1 += ph.y;
    }
    float hv0 = (act == 0) ? tanhf(h0) : (act == 1) ? fmaxf(h0, 0.f) : (act == 2) ? sigf(h0) : h0;
    float hv1 = (act == 0) ? tanhf(h1) : (act == 1) ? fmaxf(h1, 0.f) : (act == 2) ? sigf(h1) : h1;
    float s0 = sp0 + sigf(c0) * (hv0 - sp0);
    float s1 = sp1 + sigf(c1) * (hv1 - sp1);
    if (do_mean) { mean[0] += s0; mean[1] += s1; }
    if (dst_pk) {
        __nv_bfloat16 b0 = __float2bfloat16(s0), b1 = __float2bfloat16(s1);
        uint32_t hw = ((uint32_t)__bfloat16_as_ushort(b1) << 16) | __bfloat16_as_ushort(b0);
        uint32_t lw = pack_bf16x2(s0 - __bfloat162float(b0), s1 - __bfloat162float(b1));
        char* dp = dst_pk + (ej >> 7) * A_IMG + er * 272 + (ej & 127) * 2;
        *(uint32_t*)dp = hw;
        *(uint32_t*)(dp + A_HALF) = lw;
    }
}

// ---- prepass: weights -> bf16 hi/lo B images; hidden0 -> packed h; inputs -> packed x ----
__global__ void prepack_kernel(const float* __restrict__ W0, const float* __restrict__ Ws,
                               const float* __restrict__ hidden0, const float* __restrict__ inputs) {
    const int lvl_order[8] = {0, 1, 2, 3, 4, 6, 5, 7};
    const int W_ITEMS = 640 * 1024;
    const int H_ITEMS = 65536;
    const int X_ITEMS = T_STEPS * 256 * 128;           // (t, row, 4-float group)
    const int TOTAL = W_ITEMS + H_ITEMS + X_ITEMS;
    for (int idx = blockIdx.x * blockDim.x + threadIdx.x; idx < TOTAL; idx += gridDim.x * blockDim.x) {
        if (idx < W_ITEMS) {
            int g8 = idx & 7;
            int kr = (idx >> 3) & 127;
            int tt = idx >> 10;
            int sp = tt >> 4, jb = tt & 15;
            const float* src; int kbase;
            if (sp < 8) { src = W0; kbase = sp * 128; }
            else { int sp2 = sp - 8; src = Ws + (size_t)lvl_order[sp2 >> 2] * 512 * 1024; kbase = (sp2 & 3) * 128; }
            __align__(16) __nv_bfloat16 hb[8], lb[8];
            #pragma unroll
            for (int e = 0; e < 8; ++e) {
                int cidx = g8 * 8 + e;
                int nw2 = cidx >> 4, w16 = cidx & 15;
                int gc = (w16 < 8) ? (jb * 32 + nw2 * 8 + w16)
                                   : (512 + jb * 32 + nw2 * 8 + (w16 - 8));
                float wv = src[(size_t)(kbase + kr) * 1024 + gc];
                __nv_bfloat16 h = __float2bfloat16(wv);
                hb[e] = h;
                lb[e] = __float2bfloat16(wv - __bfloat162float(h));
            }
            size_t boff = (size_t)tt * B_IMG + kr * 144 + g8 * 16;
            *(uint4*)(g_Bpk + boff)          = *(const uint4*)hb;
            *(uint4*)(g_Bpk + boff + B_HALF) = *(const uint4*)lb;
        } else if (idx < W_ITEMS + H_ITEMS) {
            int i2 = idx - W_ITEMS;
            int row = i2 >> 8, col = (i2 & 255) * 2;
            float v0 = hidden0[(size_t)row * NH + col];
            float v1 = hidden0[(size_t)row * NH + col + 1];
            __nv_bfloat16 b0 = __float2bfloat16(v0), b1 = __float2bfloat16(v1);
            uint32_t hw = ((uint32_t)__bfloat16_as_ushort(b1) << 16) | __bfloat16_as_ushort(b0);
            uint32_t lw = pack_bf16x2(v0 - __bfloat162float(b0), v1 - __bfloat162float(b1));
            char* dp = g_st + ((size_t)(5 * 8 + (row >> 5)) * 4 + (col >> 7)) * A_IMG
                     + (row & 31) * 272 + (col & 127) * 2;
            *(uint32_t*)dp = hw;
            *(uint32_t*)(dp + A_HALF) = lw;
        } else {
            int i3 = idx - W_ITEMS - H_ITEMS;
            int g  = i3 & 127;                          // 4-float group within row
            int row = (i3 >> 7) & 255;
            int t   = i3 >> 15;
            int ch = g >> 5, k4 = g & 31;
            float4 v = *(const float4*)(inputs + ((size_t)t * BATCH + row) * NH + g * 4);
            __nv_bfloat16 h0 = __float2bfloat16(v.x), h1 = __float2bfloat16(v.y),
                          h2 = __float2bfloat16(v.z), h3 = __float2bfloat16(v.w);
            uint32_t ph0 = ((uint32_t)__bfloat16_as_ushort(h1) << 16) | __bfloat16_as_ushort(h0);
            uint32_t ph1 = ((uint32_t)__bfloat16_as_ushort(h3) << 16) | __bfloat16_as_ushort(h2);
            uint32_t pl0 = pack_bf16x2(v.x - __bfloat162float(h0), v.y - __bfloat162float(h1));
            uint32_t pl1 = pack_bf16x2(v.z - __bfloat162float(h2), v.w - __bfloat162float(h3));
            char* ab = g_xpk + ((size_t)((size_t)t * 8 + (row >> 5)) * 4 + ch) * A_IMG
                     + (row & 31) * 272 + k4 * 8;
            *(uint2*)ab            = make_uint2(ph0, ph1);
            *(uint2*)(ab + A_HALF) = make_uint2(pl0, pl1);
        }
    }
}

__global__ void __launch_bounds__(NTHR, 1)
rnn_kernel(float* __restrict__ out) {
    extern __shared__ char sm[];
    uint32_t smu = smem_u32(sm);
    int tid = threadIdx.x, lane = tid & 31, warp = tid >> 5;
    int kh = warp >> 2, nw = warp & 3;
    int rb = blockIdx.x >> 4, jb = blockIdx.x & 15;
    int colc = jb * 32;
    int er = tid >> 4;
    int ej = colc + (tid & 15) * 2;
    int grow = rb * 32 + er;

    char* P[6];
    #pragma unroll
    for (int s = 0; s < 6; ++s) P[s] = g_st + ((size_t)(s * 8 + rb) * 4) * A_IMG;

    if (tid == 0) {
        #pragma unroll
        for (int s = 0; s < 3; ++s) { mbar_init(smu + BAR_BF(s), 1); mbar_init(smu + BAR_BE(s), 16); }
        #pragma unroll
        for (int c = 0; c < 4; ++c) mbar_init(smu + BAR_AF(c), 1);
        mbar_init(smu + BAR_AE, 16);
    }
    __syncthreads();

    int n = 0, naf = 0, nae = 0;
    if (tid == 0) { issue_B(0, jb, smu); issue_B(1, jb, smu); }
    // prologue: x images for t=0 (region genuinely free; AE parity trick passes)
    if (tid == 0) a_bulk4(g_xpk + ((size_t)rb * 4) * A_IMG, smu, nae);
    ++naf;

    float acc[2][2][4];
    for (int t = 0; t < T_STEPS; ++t) {
        float mean[2] = {0.f, 0.f};

        // ---- L0 wave1: x chunks (A pre-issued before last barrier) ----
        ZERO_ACC(acc);
        chunks4(smu, lane, tid, kh, nw, jb, n, acc, true, (uint32_t)((naf - 1) & 1));
        if (lane == 0) MBAR_ARRIVE(smu + BAR_AE);      // per-warp release of x region
        ++nae;
        // ---- L0 wave2: h chunks ----
        if (tid == 0) a_bulk4(P[5], smu, nae);
        ++naf;
        chunks4(smu, lane, tid, kh, nw, jb, n, acc, true, (uint32_t)((naf - 1) & 1));
        red_epilogue(sm, smu, acc, lane, kh, nw, tid, P[0], 0, false, mean, er, ej, true); ++nae;
        grid_barrier(rb);

        // ---- n1 = gate(s0 @ Ws0, tanh) ----
        if (tid == 0) a_bulk4(P[0], smu, nae);
        ++naf;
        ZERO_ACC(acc);
        chunks4(smu, lane, tid, kh, nw, jb, n, acc, true, (uint32_t)((naf - 1) & 1));
        red_epilogue(sm, smu, acc, lane, kh, nw, tid, P[1], 0, true, mean, er, ej, true); ++nae;
        grid_barrier(rb);

        // ---- n2,n3,n4 (pred s1 -> A loaded once, reused) ----
        if (tid == 0) a_bulk4(P[1], smu, nae);
        ++naf;
        ZERO_ACC(acc);
        chunks4(smu, lane, tid, kh, nw, jb, n, acc, true, (uint32_t)((naf - 1) & 1));
        red_epilogue(sm, smu, acc, lane, kh, nw, tid, P[2], 1, true, mean, er, ej, false);
        ZERO_ACC(acc);
        chunks4(smu, lane, tid, kh, nw, jb, n, acc, false, 0);
        red_epilogue(sm, smu, acc, lane, kh, nw, tid, P[3], 1, true, mean, er, ej, false);
        ZERO_ACC(acc);
        chunks4(smu, lane, tid, kh, nw, jb, n, acc, false, 0);
        red_epilogue(sm, smu, acc, lane, kh, nw, tid, (char*)0, 3, true, mean, er, ej, true); ++nae;
        grid_barrier(rb);

        // ---- n5 = gate(s2 @ Ws4, tanh); n7 = gate(s3 @ Ws6, tanh) ----
        if (tid == 0) a_bulk4(P[2], smu, nae);
        ++naf;
        ZERO_ACC(acc);
        chunks4(smu, lane, tid, kh, nw, jb, n, acc, true, (uint32_t)((naf - 1) & 1));
        red_epilogue(sm, smu, acc, lane, kh, nw, tid, P[4], 0, true, mean, er, ej, true); ++nae;
        if (tid == 0) a_bulk4(P[3], smu, nae);
        ++naf;
        ZERO_ACC(acc);
        chunks4(smu, lane, tid, kh, nw, jb, n, acc, true, (uint32_t)((naf - 1) & 1));
        red_epilogue(sm, smu, acc, lane, kh, nw, tid, (char*)0, 0, true, mean, er, ej, true); ++nae;
        grid_barrier(rb);

        // ---- n6 = gate(s5 @ Ws5, sigmoid); n8 = gate(s5 @ Ws7, relu) (s5 reused) ----
        if (tid == 0) a_bulk4(P[4], smu, nae);
        ++naf;
        ZERO_ACC(acc);
        chunks4(smu, lane, tid, kh, nw, jb, n, acc, true, (uint32_t)((naf - 1) & 1));
        red_epilogue(sm, smu, acc, lane, kh, nw, tid, (char*)0, 2, true, mean, er, ej, false);
        ZERO_ACC(acc);
        chunks4(smu, lane, tid, kh, nw, jb, n, acc, false, 0);
        red_epilogue(sm, smu, acc, lane, kh, nw, tid, (char*)0, 1, true, mean, er, ej, true); ++nae;

        // issue next step's x bulks BEFORE the final barrier (x is state-independent)
        if (t + 1 < T_STEPS) {
            if (tid == 0) a_bulk4(g_xpk + ((size_t)((size_t)(t + 1) * 8 + rb) * 4) * A_IMG, smu, nae);
            ++naf;
        }

        // ---- finalize: h = mean(states 1..8); packed h + fp32 out ----
        {
            float hv0 = mean[0] * 0.125f, hv1 = mean[1] * 0.125f;
            __nv_bfloat16 b0 = __float2bfloat16(hv0), b1 = __float2bfloat16(hv1);
            uint32_t hw = ((uint32_t)__bfloat16_as_ushort(b1) << 16) | __bfloat16_as_ushort(b0);
            uint32_t lw = pack_bf16x2(hv0 - __bfloat162float(b0), hv1 - __bfloat162float(b1));
            char* dp = P[5] + (ej >> 7) * A_IMG + er * 272 + (ej & 127) * 2;
            *(uint32_t*)dp = hw;
            *(uint32_t*)(dp + A_HALF) = lw;
            *(float2*)(out + ((size_t)t * BATCH + grow) * NH + ej) = make_float2(hv0, hv1);
            if (t == T_STEPS - 1)
                *(float2*)(out + (size_t)T_STEPS * BATCH * NH + (size_t)grow * NH + ej) = make_float2(hv0, hv1);
        }
        grid_barrier(rb);
    }
}

extern "C" void kernel_launch(void* const* d_in, const int* in_sizes, int n_in,
                              void* d_out, int out_size) {
    const float* inputs = (const float*)d_in[0];
    const float* hidden = (const float*)d_in[1];
    const float* W0     = (const float*)d_in[2];
    const float* Ws     = (const float*)d_in[3];
    float* out = (float*)d_out;

    prepack_kernel<<<1024, 1024>>>(W0, Ws, hidden, inputs);
    cudaFuncSetAttribute(rnn_kernel, cudaFuncAttributeMaxDynamicSharedMemorySize, SM_TOTAL);
    rnn_kernel<<<NCTA, NTHR, SM_TOTAL>>>(out);
}

// round 14
// speedup vs baseline: 1.6230x; 1.0604x over previous
#include <cuda_runtime.h>
#include <cuda_bf16.h>
#include <math.h>
#include <stdint.h>

#define T_STEPS 400
#define BATCH   256
#define NH      512
#define NCTA    128
#define NTHR    544                   // 16 compute warps + 1 producer warp
#define TOT_CHUNKS (T_STEPS*40)

// ---- tile images ----
#define A_IMG   17408                 // 32 rows x 272B (hi 8704) + lo 8704
#define A_HALF  8704
#define B_IMG   36864                 // 128 rows x 144B (hi 18432) + lo 18432
#define B_HALF  18432

// ---- smem layout (bytes) ----
#define SM_B0   0                     // 3 rotating B slots (full/empty mbar piped)
#define SM_A    110592                // 4 chunk positions = one level's A (69632)
#define SM_RED  180224                // 4 x 8704 partials
#define SM_BAR  215040                // Bf[3], Be[3], AF[4], AE
#define SM_TOTAL 215168

#define BAR_BF(s) (SM_BAR + (s)*8)
#define BAR_BE(s) (SM_BAR + 24 + (s)*8)
#define BAR_AF(c) (SM_BAR + 48 + (c)*8)
#define BAR_AE    (SM_BAR + 80)

// compute-warp-only barrier (producer warp never joins)
#define CSYNC() asm volatile("bar.sync 1, 512;" ::: "memory")

// ---- persistent device buffers (no cudaMalloc allowed) ----
__device__ __align__(16) char g_Bpk[640ull*B_IMG];          // 40 sched-slots x 16 jb
__device__ __align__(16) char g_st [6ull*8*4*A_IMG];        // states s0,s1,s2,s3,s5,h : [st][rb][chunk]
__device__ __align__(16) char g_xpk[(size_t)T_STEPS*8*4*A_IMG];  // prepacked x images [t][rb][chunk]
__device__ unsigned long long g_barr[8*32];                 // rb-local barrier counters (monotonic)

// ---- asm helpers ----
__device__ __forceinline__ uint32_t smem_u32(const void* p) {
    uint32_t a;
    asm("{ .reg .u64 t; cvta.to.shared.u64 t, %1; cvt.u32.u64 %0, t; }" : "=r"(a) : "l"(p));
    return a;
}
#define LDM4(r, a) \
    asm volatile("ldmatrix.sync.aligned.m8n8.x4.shared.b16 {%0,%1,%2,%3}, [%4];" \
        : "=r"((r)[0]), "=r"((r)[1]), "=r"((r)[2]), "=r"((r)[3]) : "r"(a))
#define LDM4T(r, a) \
    asm volatile("ldmatrix.sync.aligned.m8n8.x4.trans.shared.b16 {%0,%1,%2,%3}, [%4];" \
        : "=r"((r)[0]), "=r"((r)[1]), "=r"((r)[2]), "=r"((r)[3]) : "r"(a))
#define MMAB(d, a, b0, b1) \
    asm volatile("mma.sync.aligned.m16n8k16.row.col.f32.bf16.bf16.f32 " \
        "{%0,%1,%2,%3},{%4,%5,%6,%7},{%8,%9},{%0,%1,%2,%3};" \
        : "+f"((d)[0]), "+f"((d)[1]), "+f"((d)[2]), "+f"((d)[3]) \
        : "r"((a)[0]), "r"((a)[1]), "r"((a)[2]), "r"((a)[3]), "r"(b0), "r"(b1))
#define MBAR_ARRIVE(bar) \
    asm volatile("mbarrier.arrive.shared.b64 _, [%0];" :: "r"(bar) : "memory")

__device__ __forceinline__ void mbar_init(uint32_t bar, uint32_t cnt) {
    asm volatile("mbarrier.init.shared.b64 [%0], %1;" :: "r"(bar), "r"(cnt) : "memory");
}
__device__ __forceinline__ void mbar_wait(uint32_t bar, uint32_t parity) {
    asm volatile(
        "{\n\t.reg .pred P;\n\tWL_%=:\n\t"
        "mbarrier.try_wait.parity.acquire.cta.shared::cta.b64 P, [%0], %1;\n\t"
        "@P bra.uni WD_%=;\n\tbra.uni WL_%=;\n\tWD_%=:\n\t}"
        :: "r"(bar), "r"(parity) : "memory");
}
__device__ __forceinline__ void bulk_g2s(uint32_t dst, const void* src, uint32_t bytes, uint32_t bar) {
    asm volatile("mbarrier.arrive.expect_tx.shared.b64 _, [%0], %1;" :: "r"(bar), "r"(bytes) : "memory");
    asm volatile("cp.async.bulk.shared::cta.global.mbarrier::complete_tx::bytes [%0], [%1], %2, [%3];"
                 :: "r"(dst), "l"(src), "r"(bytes), "r"(bar) : "memory");
}

__device__ __forceinline__ void grid_barrier(int rb) {
    CSYNC();
    if (threadIdx.x == 0) {
        __threadfence();
        unsigned long long* ctr = &g_barr[rb * 32];
        unsigned long long arr = atomicAdd(ctr, 1ULL);
        unsigned long long target = (arr / 16 + 1ULL) * 16;
        while (*(volatile unsigned long long*)ctr < target) { __nanosleep(32); }
        __threadfence();
    }
    CSYNC();
}

__device__ __forceinline__ float sigf(float x) { return 1.0f / (1.0f + expf(-x)); }
__device__ __forceinline__ uint32_t pack_bf16x2(float a, float b) {
    __nv_bfloat16 ba = __float2bfloat16(a), bb = __float2bfloat16(b);
    return ((uint32_t)__bfloat16_as_ushort(bb) << 16) | __bfloat16_as_ushort(ba);
}
__device__ __forceinline__ float bf16lo(uint32_t w) {
    return __bfloat162float(__ushort_as_bfloat16((unsigned short)(w & 0xffff)));
}
__device__ __forceinline__ float bf16hi(uint32_t w) {
    return __bfloat162float(__ushort_as_bfloat16((unsigned short)(w >> 16)));
}

// ---- producer-side primitives (executed by warp 16 lane 0 only) ----
__device__ __forceinline__ void issue_B(int q, int jb, uint32_t smu) {
    if (q >= TOT_CHUNKS) return;
    mbar_wait(smu + BAR_BE(q % 3), (uint32_t)(((q / 3) & 1) ^ 1));
    bulk_g2s(smu + SM_B0 + (q % 3) * B_IMG,
             g_Bpk + ((size_t)((q % 40) * 16 + jb)) * B_IMG, B_IMG, smu + BAR_BF(q % 3));
}
__device__ __forceinline__ void a_bulk4(const char* src, uint32_t smu, int k) {
    mbar_wait(smu + BAR_AE, (uint32_t)((k & 1) ^ 1));
    asm volatile("fence.proxy.async.shared::cta;" ::: "memory");
    #pragma unroll
    for (int c = 0; c < 4; ++c)
        bulk_g2s(smu + SM_A + c * A_IMG, src + (size_t)c * A_IMG, A_IMG, smu + BAR_AF(c));
}
__device__ __forceinline__ void epoch_wait(unsigned long long* ctr, unsigned long long need) {
    while (*(volatile unsigned long long*)ctr < need) { __nanosleep(32); }
    __threadfence();
}

// One K=128 chunk of HMMA. Warp (kh,nw): ks = kh*2+{0,1}; n cols {nw*8 (c), 32+nw*8 (h)}.
__device__ __forceinline__ void mma_chunk(uint32_t smu, int slot, int abuf_off,
                                          int lane, int kh, int nw, float acc[2][2][4]) {
    uint32_t Bb = smu + SM_B0 + slot * B_IMG;
    uint32_t Ab = smu + SM_A + abuf_off;
    int l15 = lane & 15, l16 = lane >> 4;
    #pragma unroll
    for (int ksl = 0; ksl < 2; ++ksl) {
        int ks = kh * 2 + ksl;
        uint32_t ah[2][4], al[2][4], bh[4], bl[4];
        uint32_t kb = (uint32_t)(ks * 16 + l16 * 8) * 2;
        #pragma unroll
        for (int mf = 0; mf < 2; ++mf) {
            uint32_t aa = Ab + (uint32_t)(mf * 16 + l15) * 272 + kb;
            LDM4(ah[mf], aa);
            LDM4(al[mf], aa + A_HALF);
        }
        uint32_t ba = Bb + (uint32_t)(ks * 16 + l15) * 144 + (uint32_t)(nw * 32 + l16 * 16);
        LDM4T(bh, ba);
        LDM4T(bl, ba + B_HALF);
        #pragma unroll
        for (int mf = 0; mf < 2; ++mf) {
            MMAB(acc[mf][0], ah[mf], bh[0], bh[1]);
            MMAB(acc[mf][0], ah[mf], bl[0], bl[1]);
            MMAB(acc[mf][0], al[mf], bh[0], bh[1]);
            MMAB(acc[mf][1], ah[mf], bh[2], bh[3]);
            MMAB(acc[mf][1], ah[mf], bl[2], bl[3]);
            MMAB(acc[mf][1], al[mf], bh[2], bh[3]);
        }
    }
}

// 4 chunks, consumer side only: [AF wait] -> Bf wait -> mma -> Be arrive.
__device__ __forceinline__ void chunks4(uint32_t smu, int lane, int kh, int nw,
                                        int& n, float acc[2][2][4],
                                        bool af, uint32_t afp) {
    #pragma unroll
    for (int c = 0; c < 4; ++c) {
        if (af) mbar_wait(smu + BAR_AF(c), afp);
        mbar_wait(smu + BAR_BF(n % 3), (uint32_t)((n / 3) & 1));
        mma_chunk(smu, n % 3, c * A_IMG, lane, kh, nw, acc);
        if (lane == 0) MBAR_ARRIVE(smu + BAR_BE(n % 3));
        ++n;
    }
}
#define ZERO_ACC(acc) { _Pragma("unroll") for (int _m = 0; _m < 2; ++_m) \
    _Pragma("unroll") for (int _f = 0; _f < 2; ++_f) \
    _Pragma("unroll") for (int _e = 0; _e < 4; ++_e) (acc)[_m][_f][_e] = 0.f; }

// Reduce 4 k-partials, gate vs sp (resident smem A image), store packed state.
// sp consumed BEFORE AE arrive so the region can't be overwritten mid-read.
__device__ void red_epilogue(char* sm, uint32_t smu, const float acc[2][2][4], int lane,
                             int kh, int nw, char* dst_pk, int act, bool do_mean,
                             float mean[2], int er, int ej, bool arrive_ae) {
    const char* spp = sm + SM_A + (ej >> 7) * A_IMG + er * 272 + (ej & 127) * 2;
    uint32_t hiw = *(const uint32_t*)spp;
    uint32_t low = *(const uint32_t*)(spp + A_HALF);
    float sp0 = bf16lo(hiw) + bf16lo(low);
    float sp1 = bf16hi(hiw) + bf16hi(low);
    if (arrive_ae) {
        __syncwarp();
        if (lane == 0) MBAR_ARRIVE(smu + BAR_AE);
    }
    CSYNC();                                           // all mma done; red buffer free
    float* red = (float*)(sm + SM_RED) + kh * 2176;    // 32 x 68
    int g = lane >> 2, t4 = lane & 3;
    #pragma unroll
    for (int mf = 0; mf < 2; ++mf)
        #pragma unroll
        for (int nf = 0; nf < 2; ++nf) {
            int row = mf * 16 + g, col = nf * 32 + nw * 8 + t4 * 2;
            *(float2*)(red + row * 68 + col)       = make_float2(acc[mf][nf][0], acc[mf][nf][1]);
            *(float2*)(red + (row + 8) * 68 + col) = make_float2(acc[mf][nf][2], acc[mf][nf][3]);
        }
    CSYNC();
    int lj = ej & 31;
    float c0 = 0.f, c1 = 0.f, h0 = 0.f, h1 = 0.f;
    int er2 = er, tid_ = 0; (void)tid_;
    #pragma unroll
    for (int p = 0; p < 4; ++p) {
        const float* r = (const float*)(sm + SM_RED) + p * 2176 + er2 * 68;
        float2 pc = *(const float2*)(r + lj);
        float2 ph = *(const float2*)(r + 32 + lj);
        c0 += pc.x; c1 += pc.y; h0 += ph.x; h1 += ph.y;
    }
    float hv0 = (act == 0) ? tanhf(h0) : (act == 1) ? fmaxf(h0, 0.f) : (act == 2) ? sigf(h0) : h0;
    float hv1 = (act == 0) ? tanhf(h1) : (act == 1) ? fmaxf(h1, 0.f) : (act == 2) ? sigf(h1) : h1;
    float s0 = sp0 + sigf(c0) * (hv0 - sp0);
    float s1 = sp1 + sigf(c1) * (hv1 - sp1);
    if (do_mean) { mean[0] += s0; mean[1] += s1; }
    if (dst_pk) {
        __nv_bfloat16 b0 = __float2bfloat16(s0), b1 = __float2bfloat16(s1);
        uint32_t hw = ((uint32_t)__bfloat16_as_ushort(b1) << 16) | __bfloat16_as_ushort(b0);
        uint32_t lw = pack_bf16x2(s0 - __bfloat162float(b0), s1 - __bfloat162float(b1));
        char* dp = dst_pk + (ej >> 7) * A_IMG + er * 272 + (ej & 127) * 2;
        *(uint32_t*)dp = hw;
        *(uint32_t*)(dp + A_HALF) = lw;
    }
}

// ---- prepass: weights -> bf16 hi/lo B images; hidden0 -> packed h; inputs -> packed x ----
__global__ void prepack_kernel(const float* __restrict__ W0, const float* __restrict__ Ws,
                               const float* __restrict__ hidden0, const float* __restrict__ inputs) {
    const int lvl_order[8] = {0, 1, 2, 3, 4, 6, 5, 7};
    const int W_ITEMS = 640 * 1024;
    const int H_ITEMS = 65536;
    const int X_ITEMS = T_STEPS * 256 * 128;
    const int TOTAL = W_ITEMS + H_ITEMS + X_ITEMS;
    for (int idx = blockIdx.x * blockDim.x + threadIdx.x; idx < TOTAL; idx += gridDim.x * blockDim.x) {
        if (idx < W_ITEMS) {
            int g8 = idx & 7;
            int kr = (idx >> 3) & 127;
            int tt = idx >> 10;
            int sp = tt >> 4, jb = tt & 15;
            const float* src; int kbase;
            if (sp < 8) { src = W0; kbase = sp * 128; }
            else { int sp2 = sp - 8; src = Ws + (size_t)lvl_order[sp2 >> 2] * 512 * 1024; kbase = (sp2 & 3) * 128; }
            __align__(16) __nv_bfloat16 hb[8], lb[8];
            #pragma unroll
            for (int e = 0; e < 8; ++e) {
                int cidx = g8 * 8 + e;
                int nw2 = cidx >> 4, w16 = cidx & 15;
                int gc = (w16 < 8) ? (jb * 32 + nw2 * 8 + w16)
                                   : (512 + jb * 32 + nw2 * 8 + (w16 - 8));
                float wv = src[(size_t)(kbase + kr) * 1024 + gc];
                __nv_bfloat16 h = __float2bfloat16(wv);
                hb[e] = h;
                lb[e] = __float2bfloat16(wv - __bfloat162float(h));
            }
            size_t boff = (size_t)tt * B_IMG + kr * 144 + g8 * 16;
            *(uint4*)(g_Bpk + boff)          = *(const uint4*)hb;
            *(uint4*)(g_Bpk + boff + B_HALF) = *(const uint4*)lb;
        } else if (idx < W_ITEMS + H_ITEMS) {
            int i2 = idx - W_ITEMS;
            int row = i2 >> 8, col = (i2 & 255) * 2;
            float v0 = hidden0[(size_t)row * NH + col];
            float v1 = hidden0[(size_t)row * NH + col + 1];
            __nv_bfloat16 b0 = __float2bfloat16(v0), b1 = __float2bfloat16(v1);
            uint32_t hw = ((uint32_t)__bfloat16_as_ushort(b1) << 16) | __bfloat16_as_ushort(b0);
            uint32_t lw = pack_bf16x2(v0 - __bfloat162float(b0), v1 - __bfloat162float(b1));
            char* dp = g_st + ((size_t)(5 * 8 + (row >> 5)) * 4 + (col >> 7)) * A_IMG
                     + (row & 31) * 272 + (col & 127) * 2;
            *(uint32_t*)dp = hw;
            *(uint32_t*)(dp + A_HALF) = lw;
        } else {
            int i3 = idx - W_ITEMS - H_ITEMS;
            int g  = i3 & 127;
            int row = (i3 >> 7) & 255;
            int t   = i3 >> 15;
            int ch = g >> 5, k4 = g & 31;
            float4 v = *(const float4*)(inputs + ((size_t)t * BATCH + row) * NH + g * 4);
            __nv_bfloat16 h0 = __float2bfloat16(v.x), h1 = __float2bfloat16(v.y),
                          h2 = __float2bfloat16(v.z), h3 = __float2bfloat16(v.w);
            uint32_t ph0 = ((uint32_t)__bfloat16_as_ushort(h1) << 16) | __bfloat16_as_ushort(h0);
            uint32_t ph1 = ((uint32_t)__bfloat16_as_ushort(h3) << 16) | __bfloat16_as_ushort(h2);
            uint32_t pl0 = pack_bf16x2(v.x - __bfloat162float(h0), v.y - __bfloat162float(h1));
            uint32_t pl1 = pack_bf16x2(v.z - __bfloat162float(h2), v.w - __bfloat162float(h3));
            char* ab = g_xpk + ((size_t)((size_t)t * 8 + (row >> 5)) * 4 + ch) * A_IMG
                     + (row & 31) * 272 + k4 * 8;
            *(uint2*)ab            = make_uint2(ph0, ph1);
            *(uint2*)(ab + A_HALF) = make_uint2(pl0, pl1);
        }
    }
}

__global__ void __launch_bounds__(NTHR, 1)
rnn_kernel(float* __restrict__ out) {
    extern __shared__ char sm[];
    uint32_t smu = smem_u32(sm);
    int tid = threadIdx.x, lane = tid & 31, warp = tid >> 5;
    int rb = blockIdx.x >> 4, jb = blockIdx.x & 15;
    int colc = jb * 32;

    char* P[6];
    #pragma unroll
    for (int s = 0; s < 6; ++s) P[s] = g_st + ((size_t)(s * 8 + rb) * 4) * A_IMG;

    if (tid == 0) {
        #pragma unroll
        for (int s = 0; s < 3; ++s) { mbar_init(smu + BAR_BF(s), 1); mbar_init(smu + BAR_BE(s), 16); }
        #pragma unroll
        for (int c = 0; c < 4; ++c) mbar_init(smu + BAR_AF(c), 1);
        mbar_init(smu + BAR_AE, 16);
    }
    __syncthreads();   // full block (incl. producer warp) — once, before divergence

    if (warp == 16) {
        // ---------------- producer warp (lane 0) ----------------
        if (lane == 0) {
            unsigned long long* ctr = &g_barr[rb * 32];
            unsigned long long C0 = *(volatile unsigned long long*)ctr;   // launch baseline (mult of 16)
            int n = 0, k = 0;
            issue_B(0, jb, smu); issue_B(1, jb, smu);
            a_bulk4(g_xpk + ((size_t)rb * 4) * A_IMG, smu, k); ++k;       // x(0)
            for (int t = 0; t < T_STEPS; ++t) {
                unsigned long long e = C0 + 16ull * (5ull * t);
                for (int c = 0; c < 4; ++c) { issue_B(n + 2, jb, smu); ++n; }   // wave1 B
                epoch_wait(ctr, e);                                              // h(t) ready
                a_bulk4(P[5], smu, k); ++k;
                for (int c = 0; c < 4; ++c) { issue_B(n + 2, jb, smu); ++n; }   // wave2 B
                epoch_wait(ctr, e + 16);                                         // s0 ready
                a_bulk4(P[0], smu, k); ++k;
                for (int c = 0; c < 4; ++c) { issue_B(n + 2, jb, smu); ++n; }   // n1 B
                epoch_wait(ctr, e + 32);                                         // s1 ready
                a_bulk4(P[1], smu, k); ++k;
                for (int c = 0; c < 12; ++c) { issue_B(n + 2, jb, smu); ++n; }  // n2,n3,n4 B
                epoch_wait(ctr, e + 48);                                         // s2,s3 ready
                a_bulk4(P[2], smu, k); ++k;
                for (int c = 0; c < 4; ++c) { issue_B(n + 2, jb, smu); ++n; }   // n5 B
                a_bulk4(P[3], smu, k); ++k;                                      // same epoch
                for (int c = 0; c < 4; ++c) { issue_B(n + 2, jb, smu); ++n; }   // n7 B
                epoch_wait(ctr, e + 64);                                         // s5 ready
                a_bulk4(P[4], smu, k); ++k;
                for (int c = 0; c < 8; ++c) { issue_B(n + 2, jb, smu); ++n; }   // n6,n8 B
                if (t + 1 < T_STEPS) {
                    a_bulk4(g_xpk + ((size_t)((size_t)(t + 1) * 8 + rb) * 4) * A_IMG, smu, k); ++k;
                }
            }
        }
        return;   // producer warp exits schedule; never touches bar.sync 1
    }

    // ---------------- compute warps (0..15, tid < 512) ----------------
    int kh = warp >> 2, nw = warp & 3;
    int er = tid >> 4;
    int ej = colc + (tid & 15) * 2;
    int grow = rb * 32 + er;

    int n = 0, naf = 1;     // producer already issued x(0) bulks (AF epoch 0)
    float acc[2][2][4];
    for (int t = 0; t < T_STEPS; ++t) {
        float mean[2] = {0.f, 0.f};

        // ---- L0 wave1: x chunks ----
        ZERO_ACC(acc);
        chunks4(smu, lane, kh, nw, n, acc, true, (uint32_t)((naf - 1) & 1));
        if (lane == 0) MBAR_ARRIVE(smu + BAR_AE);      // release x region
        // ---- L0 wave2: h chunks ----
        ++naf;
        chunks4(smu, lane, kh, nw, n, acc, true, (uint32_t)((naf - 1) & 1));
        red_epilogue(sm, smu, acc, lane, kh, nw, P[0], 0, false, mean, er, ej, true);
        grid_barrier(rb);

        // ---- n1 = gate(s0 @ Ws0, tanh) ----
        ++naf;
        ZERO_ACC(acc);
        chunks4(smu, lane, kh, nw, n, acc, true, (uint32_t)((naf - 1) & 1));
        red_epilogue(sm, smu, acc, lane, kh, nw, P[1], 0, true, mean, er, ej, true);
        grid_barrier(rb);

        // ---- n2,n3,n4 (pred s1, A reused) ----
        ++naf;
        ZERO_ACC(acc);
        chunks4(smu, lane, kh, nw, n, acc, true, (uint32_t)((naf - 1) & 1));
        red_epilogue(sm, smu, acc, lane, kh, nw, P[2], 1, true, mean, er, ej, false);
        ZERO_ACC(acc);
        chunks4(smu, lane, kh, nw, n, acc, false, 0);
        red_epilogue(sm, smu, acc, lane, kh, nw, P[3], 1, true, mean, er, ej, false);
        ZERO_ACC(acc);
        chunks4(smu, lane, kh, nw, n, acc, false, 0);
        red_epilogue(sm, smu, acc, lane, kh, nw, (char*)0, 3, true, mean, er, ej, true);
        grid_barrier(rb);

        // ---- n5 = gate(s2 @ Ws4, tanh); n7 = gate(s3 @ Ws6, tanh) ----
        ++naf;
        ZERO_ACC(acc);
        chunks4(smu, lane, kh, nw, n, acc, true, (uint32_t)((naf - 1) & 1));
        red_epilogue(sm, smu, acc, lane, kh, nw, P[4], 0, true, mean, er, ej, true);
        ++naf;
        ZERO_ACC(acc);
        chunks4(smu, lane, kh, nw, n, acc, true, (uint32_t)((naf - 1) & 1));
        red_epilogue(sm, smu, acc, lane, kh, nw, (char*)0, 0, true, mean, er, ej, true);
        grid_barrier(rb);

        // ---- n6 = gate(s5 @ Ws5, sigmoid); n8 = gate(s5 @ Ws7, relu) (A reused) ----
        ++naf;
        ZERO_ACC(acc);
        chunks4(smu, lane, kh, nw, n, acc, true, (uint32_t)((naf - 1) & 1));
        red_epilogue(sm, smu, acc, lane, kh, nw, (char*)0, 2, true, mean, er, ej, false);
        ZERO_ACC(acc);
        chunks4(smu, lane, kh, nw, n, acc, false, 0);
        red_epilogue(sm, smu, acc, lane, kh, nw, (char*)0, 1, true, mean, er, ej, true);

        if (t + 1 < T_STEPS) ++naf;                    // producer's x(t+1) bulks

        // ---- finalize: h = mean(states 1..8); packed h + fp32 out ----
        {
            float hv0 = mean[0] * 0.125f, hv1 = mean[1] * 0.125f;
            __nv_bfloat16 b0 = __float2bfloat16(hv0), b1 = __float2bfloat16(hv1);
            uint32_t hw = ((uint32_t)__bfloat16_as_ushort(b1) << 16) | __bfloat16_as_ushort(b0);
            uint32_t lw = pack_bf16x2(hv0 - __bfloat162float(b0), hv1 - __bfloat162float(b1));
            char* dp = P[5] + (ej >> 7) * A_IMG + er * 272 + (ej & 127) * 2;
            *(uint32_t*)dp = hw;
            *(uint32_t*)(dp + A_HALF) = lw;
            *(float2*)(out + ((size_t)t * BATCH + grow) * NH + ej) = make_float2(hv0, hv1);
            if (t == T_STEPS - 1)
                *(float2*)(out + (size_t)T_STEPS * BATCH * NH + (size_t)grow * NH + ej) = make_float2(hv0, hv1);
        }
        grid_barrier(rb);
    }
}

extern "C" void kernel_launch(void* const* d_in, const int* in_sizes, int n_in,
                              void* d_out, int out_size) {
    const float* inputs = (const float*)d_in[0];
    const float* hidden = (const float*)d_in[1];
    const float* W0     = (const float*)d_in[2];
    const float* Ws     = (const float*)d_in[3];
    float* out = (float*)d_out;

    prepack_kernel<<<1024, 1024>>>(W0, Ws, hidden, inputs);
    cudaFuncSetAttribute(rnn_kernel, cudaFuncAttributeMaxDynamicSharedMemorySize, SM_TOTAL);
    rnn_kernel<<<NCTA, NTHR, SM_TOTAL>>>(out);
}

// round 15
// speedup vs baseline: 1.8122x; 1.1166x over previous
#include <cuda_runtime.h>
#include <cuda_bf16.h>
#include <math.h>
#include <stdint.h>

#define T_STEPS 400
#define BATCH   256
#define NH      512
#define NCTA    128
#define NTHR    544                   // 16 compute warps + 1 producer warp
#define TOT_CHUNKS (T_STEPS*40)

// ---- tile images ----
#define A_IMG   17408                 // 32 rows x 272B (hi 8704) + lo 8704
#define A_HALF  8704
#define B_IMG   36864                 // 128 rows x 144B (hi 18432) + lo 18432
#define B_HALF  18432

// ---- smem layout (bytes) ----
#define SM_B0   0                     // 3 rotating B slots (full/empty mbar piped)
#define SM_A    110592                // 4 chunk positions = one level's A (69632)
#define SM_RED  180224                // 4 x 8704 partials
#define SM_BAR  215040                // Bf[3], Be[3], AF[4], AE
#define SM_TOTAL 215168

#define BAR_BF(s) (SM_BAR + (s)*8)
#define BAR_BE(s) (SM_BAR + 24 + (s)*8)
#define BAR_AF(c) (SM_BAR + 48 + (c)*8)
#define BAR_AE    (SM_BAR + 80)

// compute-warp-only barrier (producer warp never joins)
#define CSYNC() asm volatile("bar.sync 1, 512;" ::: "memory")

// ---- persistent device buffers (no cudaMalloc allowed) ----
__device__ __align__(16) char g_Bpk[640ull*B_IMG];          // 40 sched-slots x 16 jb
__device__ __align__(16) char g_st [6ull*8*4*A_IMG];        // states s0,s1,s2,s3,s5,h : [st][rb][chunk]
__device__ __align__(16) char g_xpk[(size_t)T_STEPS*8*4*A_IMG];  // prepacked x images [t][rb][chunk]
__device__ unsigned long long g_barr[8*32];                 // rb-local event counters (monotonic)
__device__ unsigned long long g_base[8];                    // per-launch baselines (set by prepack)

// ---- asm helpers ----
__device__ __forceinline__ uint32_t smem_u32(const void* p) {
    uint32_t a;
    asm("{ .reg .u64 t; cvta.to.shared.u64 t, %1; cvt.u32.u64 %0, t; }" : "=r"(a) : "l"(p));
    return a;
}
#define LDM4(r, a) \
    asm volatile("ldmatrix.sync.aligned.m8n8.x4.shared.b16 {%0,%1,%2,%3}, [%4];" \
        : "=r"((r)[0]), "=r"((r)[1]), "=r"((r)[2]), "=r"((r)[3]) : "r"(a))
#define LDM4T(r, a) \
    asm volatile("ldmatrix.sync.aligned.m8n8.x4.trans.shared.b16 {%0,%1,%2,%3}, [%4];" \
        : "=r"((r)[0]), "=r"((r)[1]), "=r"((r)[2]), "=r"((r)[3]) : "r"(a))
#define MMAB(d, a, b0, b1) \
    asm volatile("mma.sync.aligned.m16n8k16.row.col.f32.bf16.bf16.f32 " \
        "{%0,%1,%2,%3},{%4,%5,%6,%7},{%8,%9},{%0,%1,%2,%3};" \
        : "+f"((d)[0]), "+f"((d)[1]), "+f"((d)[2]), "+f"((d)[3]) \
        : "r"((a)[0]), "r"((a)[1]), "r"((a)[2]), "r"((a)[3]), "r"(b0), "r"(b1))
#define MBAR_ARRIVE(bar) \
    asm volatile("mbarrier.arrive.shared.b64 _, [%0];" :: "r"(bar) : "memory")

__device__ __forceinline__ void mbar_init(uint32_t bar, uint32_t cnt) {
    asm volatile("mbarrier.init.shared.b64 [%0], %1;" :: "r"(bar), "r"(cnt) : "memory");
}
__device__ __forceinline__ void mbar_wait(uint32_t bar, uint32_t parity) {
    asm volatile(
        "{\n\t.reg .pred P;\n\tWL_%=:\n\t"
        "mbarrier.try_wait.parity.acquire.cta.shared::cta.b64 P, [%0], %1;\n\t"
        "@P bra.uni WD_%=;\n\tbra.uni WL_%=;\n\tWD_%=:\n\t}"
        :: "r"(bar), "r"(parity) : "memory");
}
__device__ __forceinline__ void bulk_g2s(uint32_t dst, const void* src, uint32_t bytes, uint32_t bar) {
    asm volatile("mbarrier.arrive.expect_tx.shared.b64 _, [%0], %1;" :: "r"(bar), "r"(bytes) : "memory");
    asm volatile("cp.async.bulk.shared::cta.global.mbarrier::complete_tx::bytes [%0], [%1], %2, [%3];"
                 :: "r"(dst), "l"(src), "r"(bytes), "r"(bar) : "memory");
}

// Arrive-only cross-CTA event: publish this CTA's state stores. NO wait.
// (Release pattern: all-thread stores -> CTA barrier -> t0 fence + atomic.
//  Acquire side lives in the producer's epoch_wait + threadfence.)
__device__ __forceinline__ void arrive_event(int rb, int tid) {
    CSYNC();
    if (tid == 0) { __threadfence(); atomicAdd(&g_barr[rb * 32], 1ULL); }
}

__device__ __forceinline__ float sigf(float x) { return 1.0f / (1.0f + expf(-x)); }
__device__ __forceinline__ uint32_t pack_bf16x2(float a, float b) {
    __nv_bfloat16 ba = __float2bfloat16(a), bb = __float2bfloat16(b);
    return ((uint32_t)__bfloat16_as_ushort(bb) << 16) | __bfloat16_as_ushort(ba);
}
__device__ __forceinline__ float bf16lo(uint32_t w) {
    return __bfloat162float(__ushort_as_bfloat16((unsigned short)(w & 0xffff)));
}
__device__ __forceinline__ float bf16hi(uint32_t w) {
    return __bfloat162float(__ushort_as_bfloat16((unsigned short)(w >> 16)));
}

// ---- producer-side primitives (warp 16 lane 0 only) ----
__device__ __forceinline__ void issue_B(int q, int jb, uint32_t smu) {
    if (q >= TOT_CHUNKS) return;
    mbar_wait(smu + BAR_BE(q % 3), (uint32_t)(((q / 3) & 1) ^ 1));
    bulk_g2s(smu + SM_B0 + (q % 3) * B_IMG,
             g_Bpk + ((size_t)((q % 40) * 16 + jb)) * B_IMG, B_IMG, smu + BAR_BF(q % 3));
}
__device__ __forceinline__ void a_bulk4(const char* src, uint32_t smu, int k) {
    mbar_wait(smu + BAR_AE, (uint32_t)((k & 1) ^ 1));
    asm volatile("fence.proxy.async.shared::cta;" ::: "memory");
    #pragma unroll
    for (int c = 0; c < 4; ++c)
        bulk_g2s(smu + SM_A + c * A_IMG, src + (size_t)c * A_IMG, A_IMG, smu + BAR_AF(c));
}
__device__ __forceinline__ void epoch_wait(unsigned long long* ctr, unsigned long long need) {
    while (*(volatile unsigned long long*)ctr < need) { __nanosleep(32); }
    __threadfence();
}

// One K=128 chunk of HMMA. Warp (kh,nw): ks = kh*2+{0,1}; n cols {nw*8 (c), 32+nw*8 (h)}.
__device__ __forceinline__ void mma_chunk(uint32_t smu, int slot, int abuf_off,
                                          int lane, int kh, int nw, float acc[2][2][4]) {
    uint32_t Bb = smu + SM_B0 + slot * B_IMG;
    uint32_t Ab = smu + SM_A + abuf_off;
    int l15 = lane & 15, l16 = lane >> 4;
    #pragma unroll
    for (int ksl = 0; ksl < 2; ++ksl) {
        int ks = kh * 2 + ksl;
        uint32_t ah[2][4], al[2][4], bh[4], bl[4];
        uint32_t kb = (uint32_t)(ks * 16 + l16 * 8) * 2;
        #pragma unroll
        for (int mf = 0; mf < 2; ++mf) {
            uint32_t aa = Ab + (uint32_t)(mf * 16 + l15) * 272 + kb;
            LDM4(ah[mf], aa);
            LDM4(al[mf], aa + A_HALF);
        }
        uint32_t ba = Bb + (uint32_t)(ks * 16 + l15) * 144 + (uint32_t)(nw * 32 + l16 * 16);
        LDM4T(bh, ba);
        LDM4T(bl, ba + B_HALF);
        #pragma unroll
        for (int mf = 0; mf < 2; ++mf) {
            MMAB(acc[mf][0], ah[mf], bh[0], bh[1]);
            MMAB(acc[mf][0], ah[mf], bl[0], bl[1]);
            MMAB(acc[mf][0], al[mf], bh[0], bh[1]);
            MMAB(acc[mf][1], ah[mf], bh[2], bh[3]);
            MMAB(acc[mf][1], ah[mf], bl[2], bl[3]);
            MMAB(acc[mf][1], al[mf], bh[2], bh[3]);
        }
    }
}

// 4 chunks, consumer side only: [AF wait] -> Bf wait -> mma -> Be arrive.
__device__ __forceinline__ void chunks4(uint32_t smu, int lane, int kh, int nw,
                                        int& n, float acc[2][2][4],
                                        bool af, uint32_t afp) {
    #pragma unroll
    for (int c = 0; c < 4; ++c) {
        if (af) mbar_wait(smu + BAR_AF(c), afp);
        mbar_wait(smu + BAR_BF(n % 3), (uint32_t)((n / 3) & 1));
        mma_chunk(smu, n % 3, c * A_IMG, lane, kh, nw, acc);
        if (lane == 0) MBAR_ARRIVE(smu + BAR_BE(n % 3));
        ++n;
    }
}
#define ZERO_ACC(acc) { _Pragma("unroll") for (int _m = 0; _m < 2; ++_m) \
    _Pragma("unroll") for (int _f = 0; _f < 2; ++_f) \
    _Pragma("unroll") for (int _e = 0; _e < 4; ++_e) (acc)[_m][_f][_e] = 0.f; }

// Reduce 4 k-partials, gate vs sp (resident smem A image), store packed state.
__device__ void red_epilogue(char* sm, uint32_t smu, const float acc[2][2][4], int lane,
                             int kh, int nw, char* dst_pk, int act, bool do_mean,
                             float mean[2], int er, int ej, bool arrive_ae) {
    const char* spp = sm + SM_A + (ej >> 7) * A_IMG + er * 272 + (ej & 127) * 2;
    uint32_t hiw = *(const uint32_t*)spp;
    uint32_t low = *(const uint32_t*)(spp + A_HALF);
    float sp0 = bf16lo(hiw) + bf16lo(low);
    float sp1 = bf16hi(hiw) + bf16hi(low);
    if (arrive_ae) {
        __syncwarp();
        if (lane == 0) MBAR_ARRIVE(smu + BAR_AE);
    }
    CSYNC();                                           // all mma done; red buffer free
    float* red = (float*)(sm + SM_RED) + kh * 2176;    // 32 x 68
    int g = lane >> 2, t4 = lane & 3;
    #pragma unroll
    for (int mf = 0; mf < 2; ++mf)
        #pragma unroll
        for (int nf = 0; nf < 2; ++nf) {
            int row = mf * 16 + g, col = nf * 32 + nw * 8 + t4 * 2;
            *(float2*)(red + row * 68 + col)       = make_float2(acc[mf][nf][0], acc[mf][nf][1]);
            *(float2*)(red + (row + 8) * 68 + col) = make_float2(acc[mf][nf][2], acc[mf][nf][3]);
        }
    CSYNC();
    int lj = ej & 31;
    float c0 = 0.f, c1 = 0.f, h0 = 0.f, h1 = 0.f;
    #pragma unroll
    for (int p = 0; p < 4; ++p) {
        const float* r = (const float*)(sm + SM_RED) + p * 2176 + er * 68;
        float2 pc = *(const float2*)(r + lj);
        float2 ph = *(const float2*)(r + 32 + lj);
        c0 += pc.x; c1 += pc.y; h0 += ph.x; h1 += ph.y;
    }
    float hv0 = (act == 0) ? tanhf(h0) : (act == 1) ? fmaxf(h0, 0.f) : (act == 2) ? sigf(h0) : h0;
    float hv1 = (act == 0) ? tanhf(h1) : (act == 1) ? fmaxf(h1, 0.f) : (act == 2) ? sigf(h1) : h1;
    float s0 = sp0 + sigf(c0) * (hv0 - sp0);
    float s1 = sp1 + sigf(c1) * (hv1 - sp1);
    if (do_mean) { mean[0] += s0; mean[1] += s1; }
    if (dst_pk) {
        __nv_bfloat16 b0 = __float2bfloat16(s0), b1 = __float2bfloat16(s1);
        uint32_t hw = ((uint32_t)__bfloat16_as_ushort(b1) << 16) | __bfloat16_as_ushort(b0);
        uint32_t lw = pack_bf16x2(s0 - __bfloat162float(b0), s1 - __bfloat162float(b1));
        char* dp = dst_pk + (ej >> 7) * A_IMG + er * 272 + (ej & 127) * 2;
        *(uint32_t*)dp = hw;
        *(uint32_t*)(dp + A_HALF) = lw;
    }
}

// ---- prepass: pack weights/h0/x; snapshot event-counter baselines ----
__global__ void prepack_kernel(const float* __restrict__ W0, const float* __restrict__ Ws,
                               const float* __restrict__ hidden0, const float* __restrict__ inputs) {
    if (blockIdx.x == 0 && threadIdx.x < 8)
        g_base[threadIdx.x] = g_barr[threadIdx.x * 32];
    const int lvl_order[8] = {0, 1, 2, 3, 4, 6, 5, 7};
    const int W_ITEMS = 640 * 1024;
    const int H_ITEMS = 65536;
    const int X_ITEMS = T_STEPS * 256 * 128;
    const int TOTAL = W_ITEMS + H_ITEMS + X_ITEMS;
    for (int idx = blockIdx.x * blockDim.x + threadIdx.x; idx < TOTAL; idx += gridDim.x * blockDim.x) {
        if (idx < W_ITEMS) {
            int g8 = idx & 7;
            int kr = (idx >> 3) & 127;
            int tt = idx >> 10;
            int sp = tt >> 4, jb = tt & 15;
            const float* src; int kbase;
            if (sp < 8) { src = W0; kbase = sp * 128; }
            else { int sp2 = sp - 8; src = Ws + (size_t)lvl_order[sp2 >> 2] * 512 * 1024; kbase = (sp2 & 3) * 128; }
            __align__(16) __nv_bfloat16 hb[8], lb[8];
            #pragma unroll
            for (int e = 0; e < 8; ++e) {
                int cidx = g8 * 8 + e;
                int nw2 = cidx >> 4, w16 = cidx & 15;
                int gc = (w16 < 8) ? (jb * 32 + nw2 * 8 + w16)
                                   : (512 + jb * 32 + nw2 * 8 + (w16 - 8));
                float wv = src[(size_t)(kbase + kr) * 1024 + gc];
                __nv_bfloat16 h = __float2bfloat16(wv);
                hb[e] = h;
                lb[e] = __float2bfloat16(wv - __bfloat162float(h));
            }
            size_t boff = (size_t)tt * B_IMG + kr * 144 + g8 * 16;
            *(uint4*)(g_Bpk + boff)          = *(const uint4*)hb;
            *(uint4*)(g_Bpk + boff + B_HALF) = *(const uint4*)lb;
        } else if (idx < W_ITEMS + H_ITEMS) {
            int i2 = idx - W_ITEMS;
            int row = i2 >> 8, col = (i2 & 255) * 2;
            float v0 = hidden0[(size_t)row * NH + col];
            float v1 = hidden0[(size_t)row * NH + col + 1];
            __nv_bfloat16 b0 = __float2bfloat16(v0), b1 = __float2bfloat16(v1);
            uint32_t hw = ((uint32_t)__bfloat16_as_ushort(b1) << 16) | __bfloat16_as_ushort(b0);
            uint32_t lw = pack_bf16x2(v0 - __bfloat162float(b0), v1 - __bfloat162float(b1));
            char* dp = g_st + ((size_t)(5 * 8 + (row >> 5)) * 4 + (col >> 7)) * A_IMG
                     + (row & 31) * 272 + (col & 127) * 2;
            *(uint32_t*)dp = hw;
            *(uint32_t*)(dp + A_HALF) = lw;
        } else {
            int i3 = idx - W_ITEMS - H_ITEMS;
            int g  = i3 & 127;
            int row = (i3 >> 7) & 255;
            int t   = i3 >> 15;
            int ch = g >> 5, k4 = g & 31;
            float4 v = *(const float4*)(inputs + ((size_t)t * BATCH + row) * NH + g * 4);
            __nv_bfloat16 h0 = __float2bfloat16(v.x), h1 = __float2bfloat16(v.y),
                          h2 = __float2bfloat16(v.z), h3 = __float2bfloat16(v.w);
            uint32_t ph0 = ((uint32_t)__bfloat16_as_ushort(h1) << 16) | __bfloat16_as_ushort(h0);
            uint32_t ph1 = ((uint32_t)__bfloat16_as_ushort(h3) << 16) | __bfloat16_as_ushort(h2);
            uint32_t pl0 = pack_bf16x2(v.x - __bfloat162float(h0), v.y - __bfloat162float(h1));
            uint32_t pl1 = pack_bf16x2(v.z - __bfloat162float(h2), v.w - __bfloat162float(h3));
            char* ab = g_xpk + ((size_t)((size_t)t * 8 + (row >> 5)) * 4 + ch) * A_IMG
                     + (row & 31) * 272 + k4 * 8;
            *(uint2*)ab            = make_uint2(ph0, ph1);
            *(uint2*)(ab + A_HALF) = make_uint2(pl0, pl1);
        }
    }
}

__global__ void __launch_bounds__(NTHR, 1)
rnn_kernel(float* __restrict__ out) {
    extern __shared__ char sm[];
    uint32_t smu = smem_u32(sm);
    int tid = threadIdx.x, lane = tid & 31, warp = tid >> 5;
    int rb = blockIdx.x >> 4, jb = blockIdx.x & 15;
    int colc = jb * 32;

    char* P[6];
    #pragma unroll
    for (int s = 0; s < 6; ++s) P[s] = g_st + ((size_t)(s * 8 + rb) * 4) * A_IMG;

    if (tid == 0) {
        #pragma unroll
        for (int s = 0; s < 3; ++s) { mbar_init(smu + BAR_BF(s), 1); mbar_init(smu + BAR_BE(s), 16); }
        #pragma unroll
        for (int c = 0; c < 4; ++c) mbar_init(smu + BAR_AF(c), 1);
        mbar_init(smu + BAR_AE, 16);
    }
    __syncthreads();   // full block (incl. producer warp) — once, before divergence

    if (warp == 16) {
        // ---------------- producer warp (lane 0) ----------------
        if (lane == 0) {
            unsigned long long* ctr = &g_barr[rb * 32];
            unsigned long long B = g_base[rb];          // race-free launch baseline
            int n = 0, k = 0;
            issue_B(0, jb, smu); issue_B(1, jb, smu);
            a_bulk4(g_xpk + ((size_t)rb * 4) * A_IMG, smu, k); ++k;       // x(0)
            for (int t = 0; t < T_STEPS; ++t) {
                unsigned long long e = B + 80ull * t;   // 16 arrivals x 5 events/step
                for (int c = 0; c < 4; ++c) { issue_B(n + 2, jb, smu); ++n; }   // wave1 B
                epoch_wait(ctr, e);                                              // E5(t-1): h(t)
                a_bulk4(P[5], smu, k); ++k;
                for (int c = 0; c < 4; ++c) { issue_B(n + 2, jb, smu); ++n; }   // wave2 B
                epoch_wait(ctr, e + 16);                                         // E1: s0
                a_bulk4(P[0], smu, k); ++k;
                for (int c = 0; c < 4; ++c) { issue_B(n + 2, jb, smu); ++n; }   // n1 B
                epoch_wait(ctr, e + 32);                                         // E2: s1
                a_bulk4(P[1], smu, k); ++k;
                for (int c = 0; c < 12; ++c) { issue_B(n + 2, jb, smu); ++n; }  // n2,n3,n4 B
                epoch_wait(ctr, e + 48);                                         // E3: s2,s3
                a_bulk4(P[2], smu, k); ++k;
                for (int c = 0; c < 4; ++c) { issue_B(n + 2, jb, smu); ++n; }   // n5 B
                a_bulk4(P[3], smu, k); ++k;
                for (int c = 0; c < 4; ++c) { issue_B(n + 2, jb, smu); ++n; }   // n7 B
                epoch_wait(ctr, e + 64);                                         // E4: s5
                a_bulk4(P[4], smu, k); ++k;
                for (int c = 0; c < 8; ++c) { issue_B(n + 2, jb, smu); ++n; }   // n6,n8 B
                if (t + 1 < T_STEPS) {
                    a_bulk4(g_xpk + ((size_t)((size_t)(t + 1) * 8 + rb) * 4) * A_IMG, smu, k); ++k;
                }
            }
        }
        return;   // producer warp never touches bar.sync 1
    }

    // ---------------- compute warps (0..15, tid < 512) ----------------
    int kh = warp >> 2, nw = warp & 3;
    int er = tid >> 4;
    int ej = colc + (tid & 15) * 2;
    int grow = rb * 32 + er;

    int n = 0, naf = 1;     // producer already issued x(0) bulks (AF epoch 0)
    float acc[2][2][4];
    for (int t = 0; t < T_STEPS; ++t) {
        float mean[2] = {0.f, 0.f};

        // ---- L0 wave1: x chunks ----
        ZERO_ACC(acc);
        chunks4(smu, lane, kh, nw, n, acc, true, (uint32_t)((naf - 1) & 1));
        if (lane == 0) MBAR_ARRIVE(smu + BAR_AE);      // release x region
        // ---- L0 wave2: h chunks ----
        ++naf;
        chunks4(smu, lane, kh, nw, n, acc, true, (uint32_t)((naf - 1) & 1));
        red_epilogue(sm, smu, acc, lane, kh, nw, P[0], 0, false, mean, er, ej, true);
        arrive_event(rb, tid);                          // E1: s0 published

        // ---- n1 = gate(s0 @ Ws0, tanh) ----
        ++naf;
        ZERO_ACC(acc);
        chunks4(smu, lane, kh, nw, n, acc, true, (uint32_t)((naf - 1) & 1));
        red_epilogue(sm, smu, acc, lane, kh, nw, P[1], 0, true, mean, er, ej, true);
        arrive_event(rb, tid);                          // E2: s1 published

        // ---- n2,n3,n4 (pred s1, A reused) ----
        ++naf;
        ZERO_ACC(acc);
        chunks4(smu, lane, kh, nw, n, acc, true, (uint32_t)((naf - 1) & 1));
        red_epilogue(sm, smu, acc, lane, kh, nw, P[2], 1, true, mean, er, ej, false);
        ZERO_ACC(acc);
        chunks4(smu, lane, kh, nw, n, acc, false, 0);
        red_epilogue(sm, smu, acc, lane, kh, nw, P[3], 1, true, mean, er, ej, false);
        arrive_event(rb, tid);                          // E3: s2,s3 published (before n4!)
        ZERO_ACC(acc);
        chunks4(smu, lane, kh, nw, n, acc, false, 0);
        red_epilogue(sm, smu, acc, lane, kh, nw, (char*)0, 3, true, mean, er, ej, true);

        // ---- n5 = gate(s2 @ Ws4, tanh) ----
        ++naf;
        ZERO_ACC(acc);
        chunks4(smu, lane, kh, nw, n, acc, true, (uint32_t)((naf - 1) & 1));
        red_epilogue(sm, smu, acc, lane, kh, nw, P[4], 0, true, mean, er, ej, true);
        arrive_event(rb, tid);                          // E4: s5 published (before n7!)
        // ---- n7 = gate(s3 @ Ws6, tanh) ----
        ++naf;
        ZERO_ACC(acc);
        chunks4(smu, lane, kh, nw, n, acc, true, (uint32_t)((naf - 1) & 1));
        red_epilogue(sm, smu, acc, lane, kh, nw, (char*)0, 0, true, mean, er, ej, true);

        // ---- n6 = gate(s5 @ Ws5, sigmoid); n8 = gate(s5 @ Ws7, relu) (A reused) ----
        ++naf;
        ZERO_ACC(acc);
        chunks4(smu, lane, kh, nw, n, acc, true, (uint32_t)((naf - 1) & 1));
        red_epilogue(sm, smu, acc, lane, kh, nw, (char*)0, 2, true, mean, er, ej, false);
        ZERO_ACC(acc);
        chunks4(smu, lane, kh, nw, n, acc, false, 0);
        red_epilogue(sm, smu, acc, lane, kh, nw, (char*)0, 1, true, mean, er, ej, true);

        if (t + 1 < T_STEPS) ++naf;                    // producer's x(t+1) bulks

        // ---- finalize: h = mean(states 1..8); packed h + fp32 out ----
        {
            float hv0 = mean[0] * 0.125f, hv1 = mean[1] * 0.125f;
            __nv_bfloat16 b0 = __float2bfloat16(hv0), b1 = __float2bfloat16(hv1);
            uint32_t hw = ((uint32_t)__bfloat16_as_ushort(b1) << 16) | __bfloat16_as_ushort(b0);
            uint32_t lw = pack_bf16x2(hv0 - __bfloat162float(b0), hv1 - __bfloat162float(b1));
            char* dp = P[5] + (ej >> 7) * A_IMG + er * 272 + (ej & 127) * 2;
            *(uint32_t*)dp = hw;
            *(uint32_t*)(dp + A_HALF) = lw;
            *(float2*)(out + ((size_t)t * BATCH + grow) * NH + ej) = make_float2(hv0, hv1);
            if (t == T_STEPS - 1)
                *(float2*)(out + (size_t)T_STEPS * BATCH * NH + (size_t)grow * NH + ej) = make_float2(hv0, hv1);
        }
        arrive_event(rb, tid);                          // E5: h published
    }
}

extern "C" void kernel_launch(void* const* d_in, const int* in_sizes, int n_in,
                              void* d_out, int out_size) {
    const float* inputs = (const float*)d_in[0];
    const float* hidden = (const float*)d_in[1];
    const float* W0     = (const float*)d_in[2];
    const float* Ws     = (const float*)d_in[3];
    float* out = (float*)d_out;

    prepack_kernel<<<1024, 1024>>>(W0, Ws, hidden, inputs);
    cudaFuncSetAttribute(rnn_kernel, cudaFuncAttributeMaxDynamicSharedMemorySize, SM_TOTAL);
    rnn_kernel<<<NCTA, NTHR, SM_TOTAL>>>(out);
}